// round 1
// baseline (speedup 1.0000x reference)
#include <cuda_runtime.h>
#include <math.h>

// ---------------- problem constants ----------------
#define BQ   4
#define SQ   512
#define DQ   768
#define HQ   12
#define HDQ  64
#define LQ   12
#define VQ   50257
#define FFQ  3072
#define NT   (BQ*SQ)   // 2048 tokens

// ---------------- static scratch (no allocs allowed) ----------------
__device__ __align__(128) float g_h  [NT*DQ];
__device__ __align__(128) float g_hn [NT*DQ];
__device__ __align__(128) float g_q  [NT*DQ];
__device__ __align__(128) float g_k  [NT*DQ];
__device__ __align__(128) float g_v  [NT*DQ];
__device__ __align__(128) float g_ctx[NT*DQ];
__device__ __align__(128) float g_ff [NT*FFQ];
__device__ __align__(128) float g_attn[(long)BQ*HQ*SQ*SQ];  // 12.58M floats

// ---------------- helpers ----------------
__device__ __forceinline__ float gelu_f(float x) {
    const float c = 0.7978845608028654f; // sqrt(2/pi)
    float x3 = x * x * x;
    return 0.5f * x * (1.0f + tanhf(c * (x + 0.044715f * x3)));
}

// ---------------- embedding ----------------
__global__ void gpt_embed(const int* __restrict__ x, const float* __restrict__ tok,
                          const float* __restrict__ pos, float* __restrict__ h) {
    int i = blockIdx.x * blockDim.x + threadIdx.x;
    if (i < NT * DQ) {
        int t = i / DQ, d = i - t * DQ;
        int s = t & (SQ - 1);
        h[i] = tok[(long)x[t] * DQ + d] + pos[s * DQ + d];
    }
}

// ---------------- layernorm: one block per token ----------------
__global__ void gpt_ln(const float* __restrict__ in, const float* __restrict__ scale,
                       const float* __restrict__ shift, float* __restrict__ out) {
    int t = blockIdx.x;
    const float* row = in + (long)t * DQ;
    __shared__ float red[256];
    int tid = threadIdx.x;

    float s = 0.f;
    for (int d = tid; d < DQ; d += 256) s += row[d];
    red[tid] = s; __syncthreads();
    for (int o = 128; o > 0; o >>= 1) { if (tid < o) red[tid] += red[tid + o]; __syncthreads(); }
    float mean = red[0] * (1.0f / DQ); __syncthreads();

    float sq = 0.f;
    for (int d = tid; d < DQ; d += 256) { float v = row[d] - mean; sq += v * v; }
    red[tid] = sq; __syncthreads();
    for (int o = 128; o > 0; o >>= 1) { if (tid < o) red[tid] += red[tid + o]; __syncthreads(); }
    float inv = rsqrtf(red[0] * (1.0f / DQ) + 1e-5f);

    float* orow = out + (long)t * DQ;
    for (int d = tid; d < DQ; d += 256)
        orow[d] = scale[d] * (row[d] - mean) * inv + shift[d];
}

// ---------------- generic 128x128x8 SGEMM ----------------
// C[M,N] = A[M,K] @ B[K,N]  (row-major). EPI: 0 none, 1 +bias, 2 +bias+res, 3 gelu(x+bias)
// Batch (grid.z): offA = z*sA;  offB = (z/zdiv)*sBo + (z%zdiv)*sBi;  offC = (z/zdiv)*sCo + (z%zdiv)*sCi
template<int EPI, bool GUARD>
__global__ void __launch_bounds__(256)
gpt_sgemm(const float* __restrict__ A, const float* __restrict__ Bm,
          const float* __restrict__ bias, const float* __restrict__ res,
          float* __restrict__ C,
          int M, int N, int K, int lda, int ldb, int ldc,
          long sA, int zdiv, long sBo, long sBi, long sCo, long sCi) {
    constexpr int BM = 128, BN = 128, BK = 8, TM = 8, TN = 8;
    __shared__ float As[BK][BM];
    __shared__ float Bs[BK][BN];

    int z = blockIdx.z;
    A  += (long)z * sA;
    Bm += (long)(z / zdiv) * sBo + (long)(z % zdiv) * sBi;
    C  += (long)(z / zdiv) * sCo + (long)(z % zdiv) * sCi;

    int bm = blockIdx.y * BM, bn = blockIdx.x * BN;
    int tid = threadIdx.x;
    int arow = tid >> 1, acol = (tid & 1) * 4;      // A tile: 128 x 8
    int brow = tid >> 5, bcol = (tid & 31) * 4;     // B tile: 8 x 128
    int tx = (tid & 15) * TN;
    int ty = (tid >> 4) * TM;

    float acc[TM][TN] = {};

    for (int k0 = 0; k0 < K; k0 += BK) {
        if (!GUARD) {
            float4 a = *(const float4*)(A + (long)(bm + arow) * lda + k0 + acol);
            As[acol + 0][arow] = a.x; As[acol + 1][arow] = a.y;
            As[acol + 2][arow] = a.z; As[acol + 3][arow] = a.w;
            float4 b = *(const float4*)(Bm + (long)(k0 + brow) * ldb + bn + bcol);
            *(float4*)&Bs[brow][bcol] = b;
        } else {
            int gr = bm + arow;
            #pragma unroll
            for (int i = 0; i < 4; i++)
                As[acol + i][arow] = (gr < M) ? A[(long)gr * lda + k0 + acol + i] : 0.f;
            int gk = k0 + brow;
            #pragma unroll
            for (int i = 0; i < 4; i++) {
                int gn = bn + bcol + i;
                Bs[brow][bcol + i] = (gn < N) ? Bm[(long)gk * ldb + gn] : 0.f;
            }
        }
        __syncthreads();
        #pragma unroll
        for (int kk = 0; kk < BK; kk++) {
            float ar[TM], br[TN];
            #pragma unroll
            for (int i = 0; i < TM; i++) ar[i] = As[kk][ty + i];
            #pragma unroll
            for (int j = 0; j < TN; j++) br[j] = Bs[kk][tx + j];
            #pragma unroll
            for (int i = 0; i < TM; i++)
                #pragma unroll
                for (int j = 0; j < TN; j++)
                    acc[i][j] += ar[i] * br[j];
        }
        __syncthreads();
    }

    #pragma unroll
    for (int i = 0; i < TM; i++) {
        int gm = bm + ty + i;
        if (GUARD && gm >= M) continue;
        #pragma unroll
        for (int j = 0; j < TN; j++) {
            int gn = bn + tx + j;
            if (GUARD && gn >= N) continue;
            float v = acc[i][j];
            if (EPI >= 1) v += bias[gn];
            if (EPI == 3) v = gelu_f(v);
            if (EPI == 2) v += res[(long)gm * ldc + gn];
            C[(long)gm * ldc + gn] = v;
        }
    }
}

// QKV: one launch, grid.z selects {q,k,v} weight/output pair. M=NT, N=K=DQ.
__global__ void __launch_bounds__(256)
gpt_sgemm_qkv(const float* __restrict__ A,
              const float* __restrict__ Wq, const float* __restrict__ Wk,
              const float* __restrict__ Wv,
              float* __restrict__ Oq, float* __restrict__ Ok, float* __restrict__ Ov) {
    constexpr int BM = 128, BN = 128, BK = 8, TM = 8, TN = 8;
    __shared__ float As[BK][BM];
    __shared__ float Bs[BK][BN];
    int z = blockIdx.z;
    const float* Bm = (z == 0) ? Wq : (z == 1) ? Wk : Wv;
    float* C = (z == 0) ? Oq : (z == 1) ? Ok : Ov;

    int bm = blockIdx.y * BM, bn = blockIdx.x * BN;
    int tid = threadIdx.x;
    int arow = tid >> 1, acol = (tid & 1) * 4;
    int brow = tid >> 5, bcol = (tid & 31) * 4;
    int tx = (tid & 15) * TN, ty = (tid >> 4) * TM;
    float acc[TM][TN] = {};
    for (int k0 = 0; k0 < DQ; k0 += BK) {
        float4 a = *(const float4*)(A + (long)(bm + arow) * DQ + k0 + acol);
        As[acol + 0][arow] = a.x; As[acol + 1][arow] = a.y;
        As[acol + 2][arow] = a.z; As[acol + 3][arow] = a.w;
        float4 b = *(const float4*)(Bm + (long)(k0 + brow) * DQ + bn + bcol);
        *(float4*)&Bs[brow][bcol] = b;
        __syncthreads();
        #pragma unroll
        for (int kk = 0; kk < BK; kk++) {
            float ar[TM], br[TN];
            #pragma unroll
            for (int i = 0; i < TM; i++) ar[i] = As[kk][ty + i];
            #pragma unroll
            for (int j = 0; j < TN; j++) br[j] = Bs[kk][tx + j];
            #pragma unroll
            for (int i = 0; i < TM; i++)
                #pragma unroll
                for (int j = 0; j < TN; j++)
                    acc[i][j] += ar[i] * br[j];
        }
        __syncthreads();
    }
    #pragma unroll
    for (int i = 0; i < TM; i++)
        #pragma unroll
        for (int j = 0; j < TN; j++)
            C[(long)(bm + ty + i) * DQ + bn + tx + j] = acc[i][j];
}

// ---------------- attention scores + causal softmax ----------------
// grid (SQ/QPB, B*H), 128 threads. Writes normalized attn (zeros where masked).
#define QPB 8
__global__ void gpt_attn(const float* __restrict__ Q, const float* __restrict__ Kx,
                         float* __restrict__ attn) {
    int z = blockIdx.y;
    int b = z / HQ, hh = z - b * HQ;
    int q0 = blockIdx.x * QPB;
    int tid = threadIdx.x;

    __shared__ float qv[QPB][HDQ];
    __shared__ float row[QPB][SQ];
    __shared__ float red[128];

    for (int i = tid; i < QPB * HDQ; i += 128) {
        int qq = i / HDQ, d = i - qq * HDQ;
        qv[qq][d] = Q[(long)((b * SQ + q0 + qq) * DQ) + hh * HDQ + d];
    }
    __syncthreads();

    for (int kk = tid; kk < SQ; kk += 128) {
        const float* krow = Kx + (long)((b * SQ + kk) * DQ) + hh * HDQ;
        float acc[QPB] = {};
        #pragma unroll
        for (int d = 0; d < HDQ; d += 4) {
            float4 kv4 = *(const float4*)(krow + d);
            #pragma unroll
            for (int qq = 0; qq < QPB; qq++) {
                acc[qq] += qv[qq][d] * kv4.x + qv[qq][d + 1] * kv4.y
                         + qv[qq][d + 2] * kv4.z + qv[qq][d + 3] * kv4.w;
            }
        }
        #pragma unroll
        for (int qq = 0; qq < QPB; qq++)
            row[qq][kk] = (kk <= q0 + qq) ? acc[qq] * 0.125f : -1e30f;
    }
    __syncthreads();

    for (int qq = 0; qq < QPB; qq++) {
        float m = -1e30f;
        for (int kk = tid; kk < SQ; kk += 128) m = fmaxf(m, row[qq][kk]);
        red[tid] = m; __syncthreads();
        for (int o = 64; o > 0; o >>= 1) { if (tid < o) red[tid] = fmaxf(red[tid], red[tid + o]); __syncthreads(); }
        m = red[0]; __syncthreads();

        float ss = 0.f;
        for (int kk = tid; kk < SQ; kk += 128) {
            float e = expf(row[qq][kk] - m);
            row[qq][kk] = e;
            ss += e;
        }
        red[tid] = ss; __syncthreads();
        for (int o = 64; o > 0; o >>= 1) { if (tid < o) red[tid] += red[tid + o]; __syncthreads(); }
        float inv = 1.0f / red[0]; __syncthreads();

        float* arow = attn + ((long)z * SQ + q0 + qq) * SQ;
        for (int kk = tid; kk < SQ; kk += 128) arow[kk] = row[qq][kk] * inv;
    }
}

// ---------------- host orchestration ----------------
extern "C" void kernel_launch(void* const* d_in, const int* in_sizes, int n_in,
                              void* d_out, int out_size) {
    const int*   x    = (const int*)  d_in[0];
    const float* tok  = (const float*)d_in[1];
    const float* pos  = (const float*)d_in[2];
    const float* ln1s = (const float*)d_in[3];
    const float* ln1b = (const float*)d_in[4];
    const float* wq   = (const float*)d_in[5];
    const float* wk   = (const float*)d_in[6];
    const float* wv   = (const float*)d_in[7];
    const float* wo   = (const float*)d_in[8];
    const float* bo   = (const float*)d_in[9];
    const float* ln2s = (const float*)d_in[10];
    const float* ln2b = (const float*)d_in[11];
    const float* w1   = (const float*)d_in[12];
    const float* b1   = (const float*)d_in[13];
    const float* w2   = (const float*)d_in[14];
    const float* b2   = (const float*)d_in[15];
    const float* fs   = (const float*)d_in[16];
    const float* fb   = (const float*)d_in[17];
    const float* wout = (const float*)d_in[18];
    float* out = (float*)d_out;

    float *h, *hn, *q, *k, *v, *ctx, *ff, *attn;
    cudaGetSymbolAddress((void**)&h,    g_h);
    cudaGetSymbolAddress((void**)&hn,   g_hn);
    cudaGetSymbolAddress((void**)&q,    g_q);
    cudaGetSymbolAddress((void**)&k,    g_k);
    cudaGetSymbolAddress((void**)&v,    g_v);
    cudaGetSymbolAddress((void**)&ctx,  g_ctx);
    cudaGetSymbolAddress((void**)&ff,   g_ff);
    cudaGetSymbolAddress((void**)&attn, g_attn);

    gpt_embed<<<(NT * DQ + 255) / 256, 256>>>(x, tok, pos, h);

    dim3 gD  (DQ / 128,  NT / 128);        // (6,16)   N=768 gemms
    dim3 gQKV(DQ / 128,  NT / 128, 3);     // (6,16,3) fused qkv
    dim3 gFF (FFQ / 128, NT / 128);        // (24,16)  N=3072
    dim3 gCtx(1, SQ / 128, BQ * HQ);       // (1,4,48) ctx batched
    dim3 gAtt(SQ / QPB, BQ * HQ);          // (64,48)

    for (int l = 0; l < LQ; l++) {
        const float* Wq = wq + (long)l * DQ * DQ;
        const float* Wk = wk + (long)l * DQ * DQ;
        const float* Wv = wv + (long)l * DQ * DQ;
        const float* Wo = wo + (long)l * DQ * DQ;
        const float* W1 = w1 + (long)l * DQ * FFQ;
        const float* W2 = w2 + (long)l * FFQ * DQ;

        gpt_ln<<<NT, 256>>>(h, ln1s + l * DQ, ln1b + l * DQ, hn);

        gpt_sgemm_qkv<<<gQKV, 256>>>(hn, Wq, Wk, Wv, q, k, v);

        gpt_attn<<<gAtt, 128>>>(q, k, attn);

        // ctx[bh] = attn[bh] @ v[bh]  : M=512, N=64, K=512 (guarded: N<128)
        gpt_sgemm<0, true><<<gCtx, 256>>>(attn, v, nullptr, nullptr, ctx,
            SQ, HDQ, SQ, SQ, DQ, DQ,
            (long)SQ * SQ, HQ, (long)SQ * DQ, (long)HDQ, (long)SQ * DQ, (long)HDQ);

        // h = h + ctx @ Wo + bo
        gpt_sgemm<2, false><<<gD, 256>>>(ctx, Wo, bo + l * DQ, h, h,
            NT, DQ, DQ, DQ, DQ, DQ, 0, 1, 0, 0, 0, 0);

        gpt_ln<<<NT, 256>>>(h, ln2s + l * DQ, ln2b + l * DQ, hn);

        // ff = gelu(hn @ W1 + b1)
        gpt_sgemm<3, false><<<gFF, 256>>>(hn, W1, b1 + l * FFQ, nullptr, ff,
            NT, FFQ, DQ, DQ, FFQ, FFQ, 0, 1, 0, 0, 0, 0);

        // h = h + ff @ W2 + b2
        gpt_sgemm<2, false><<<gD, 256>>>(ff, W2, b2 + l * DQ, h, h,
            NT, DQ, FFQ, FFQ, DQ, DQ, 0, 1, 0, 0, 0, 0);
    }

    gpt_ln<<<NT, 256>>>(h, fs, fb, hn);

    // logits = hn @ w_out : M=2048, N=50257 (guarded), K=768
    dim3 gV((VQ + 127) / 128, NT / 128);
    gpt_sgemm<0, true><<<gV, 256>>>(hn, wout, nullptr, nullptr, out,
        NT, VQ, DQ, DQ, VQ, VQ, 0, 1, 0, 0, 0, 0);
}

// round 3
// speedup vs baseline: 1.3387x; 1.3387x over previous
#include <cuda_runtime.h>
#include <math.h>

// ---------------- problem constants ----------------
#define BQ   4
#define SQ   512
#define DQ   768
#define HQ   12
#define HDQ  64
#define LQ   12
#define VQ   50257
#define FFQ  3072
#define NT   (BQ*SQ)   // 2048 tokens

// ---------------- static scratch (no allocs allowed) ----------------
__device__ __align__(128) float g_h  [NT*DQ];
__device__ __align__(128) float g_hn [NT*DQ];
__device__ __align__(128) float g_q  [NT*DQ];
__device__ __align__(128) float g_k  [NT*DQ];
__device__ __align__(128) float g_v  [NT*DQ];
__device__ __align__(128) float g_ctx[NT*DQ];
__device__ __align__(128) float g_ff [NT*FFQ];

// ---------------- helpers ----------------
__device__ __forceinline__ float gelu_f(float x) {
    const float c = 0.7978845608028654f; // sqrt(2/pi)
    float x3 = x * x * x;
    return 0.5f * x * (1.0f + tanhf(c * (x + 0.044715f * x3)));
}

// ---------------- embedding ----------------
__global__ void gpt_embed(const int* __restrict__ x, const float* __restrict__ tok,
                          const float* __restrict__ pos, float* __restrict__ h) {
    int i = blockIdx.x * blockDim.x + threadIdx.x;
    if (i < NT * DQ) {
        int t = i / DQ, d = i - t * DQ;
        int s = t & (SQ - 1);
        h[i] = tok[(long)x[t] * DQ + d] + pos[s * DQ + d];
    }
}

// ---------------- layernorm: one block per token ----------------
__global__ void gpt_ln(const float* __restrict__ in, const float* __restrict__ scale,
                       const float* __restrict__ shift, float* __restrict__ out) {
    int t = blockIdx.x;
    const float* row = in + (long)t * DQ;
    __shared__ float red[256];
    int tid = threadIdx.x;

    float s = 0.f;
    for (int d = tid; d < DQ; d += 256) s += row[d];
    red[tid] = s; __syncthreads();
    for (int o = 128; o > 0; o >>= 1) { if (tid < o) red[tid] += red[tid + o]; __syncthreads(); }
    float mean = red[0] * (1.0f / DQ); __syncthreads();

    float sq = 0.f;
    for (int d = tid; d < DQ; d += 256) { float v = row[d] - mean; sq += v * v; }
    red[tid] = sq; __syncthreads();
    for (int o = 128; o > 0; o >>= 1) { if (tid < o) red[tid] += red[tid + o]; __syncthreads(); }
    float inv = rsqrtf(red[0] * (1.0f / DQ) + 1e-5f);

    float* orow = out + (long)t * DQ;
    for (int d = tid; d < DQ; d += 256)
        orow[d] = scale[d] * (row[d] - mean) * inv + shift[d];
}

// ---------------- fast SGEMM with register prefetch ----------------
// C[M,N] = A @ B, M,N multiples of tile, K multiple of 8.
// EPI: 0 none, 2 +bias+res, 3 gelu(x+bias)
// VECB: float4 B loads (requires ldb % 4 == 0 and bn/bcol alignment)
template<int EPI, int BM, bool VECB>
__global__ void __launch_bounds__(256)
gpt_gemm_f(const float* __restrict__ A, const float* __restrict__ Bm,
           const float* __restrict__ bias, const float* __restrict__ res,
           float* __restrict__ C, int M, int N, int K, int lda, int ldb, int ldc) {
    constexpr int BN = 128, BK = 8;
    constexpr int TM = BM / 16, TN = 8;
    __shared__ float As[BK][BM];
    __shared__ float Bs[BK][BN];

    int bm = blockIdx.y * BM, bn = blockIdx.x * BN;
    int tid = threadIdx.x;
    int brow = tid >> 5, bcol = (tid & 31) * 4;
    int arow, acol;
    if (BM == 128) { arow = tid >> 1; acol = (tid & 1) * 4; }
    else           { arow = tid >> 2; acol = (tid & 3) * 2; }
    int tx = (tid & 15) * TN, ty = (tid >> 4) * TM;

    const float* Aptr = A + (long)(bm + arow) * lda + acol;
    const float* Bptr = Bm + (long)brow * ldb + bn + bcol;

    float4 pa; float2 pa2;
    if (BM == 128) pa = *(const float4*)Aptr; else pa2 = *(const float2*)Aptr;
    float pb[4];
    if (VECB) { float4 t = *(const float4*)Bptr; pb[0]=t.x; pb[1]=t.y; pb[2]=t.z; pb[3]=t.w; }
    else { pb[0]=Bptr[0]; pb[1]=Bptr[1]; pb[2]=Bptr[2]; pb[3]=Bptr[3]; }

    float acc[TM][TN] = {};

    for (int k0 = 0; k0 < K; k0 += BK) {
        if (BM == 128) {
            As[acol + 0][arow] = pa.x; As[acol + 1][arow] = pa.y;
            As[acol + 2][arow] = pa.z; As[acol + 3][arow] = pa.w;
        } else {
            As[acol + 0][arow] = pa2.x; As[acol + 1][arow] = pa2.y;
        }
        Bs[brow][bcol + 0] = pb[0]; Bs[brow][bcol + 1] = pb[1];
        Bs[brow][bcol + 2] = pb[2]; Bs[brow][bcol + 3] = pb[3];
        __syncthreads();
        if (k0 + BK < K) {
            if (BM == 128) pa = *(const float4*)(Aptr + k0 + BK);
            else           pa2 = *(const float2*)(Aptr + k0 + BK);
            const float* bp = Bptr + (long)(k0 + BK) * ldb;
            if (VECB) { float4 t = *(const float4*)bp; pb[0]=t.x; pb[1]=t.y; pb[2]=t.z; pb[3]=t.w; }
            else { pb[0]=bp[0]; pb[1]=bp[1]; pb[2]=bp[2]; pb[3]=bp[3]; }
        }
        #pragma unroll
        for (int kk = 0; kk < BK; kk++) {
            float ar[TM], br[TN];
            #pragma unroll
            for (int i = 0; i < TM; i++) ar[i] = As[kk][ty + i];
            #pragma unroll
            for (int j = 0; j < TN; j++) br[j] = Bs[kk][tx + j];
            #pragma unroll
            for (int i = 0; i < TM; i++)
                #pragma unroll
                for (int j = 0; j < TN; j++)
                    acc[i][j] += ar[i] * br[j];
        }
        __syncthreads();
    }

    #pragma unroll
    for (int i = 0; i < TM; i++) {
        int gm = bm + ty + i;
        #pragma unroll
        for (int j = 0; j < TN; j++) {
            int gn = bn + tx + j;
            float v = acc[i][j];
            if (EPI >= 2) v += bias[gn];
            if (EPI == 3) v = gelu_f(v);
            if (EPI == 2) v += res[(long)gm * ldc + gn];
            C[(long)gm * ldc + gn] = v;
        }
    }
}

// ---------------- guarded SGEMM (vocab remainder only) ----------------
__global__ void __launch_bounds__(256)
gpt_gemm_g(const float* __restrict__ A, const float* __restrict__ Bm,
           float* __restrict__ C, int M, int N, int K, int lda, int ldb, int ldc) {
    constexpr int BM = 128, BN = 128, BK = 8, TM = 8, TN = 8;
    __shared__ float As[BK][BM];
    __shared__ float Bs[BK][BN];
    int bm = blockIdx.y * BM, bn = blockIdx.x * BN;
    int tid = threadIdx.x;
    int arow = tid >> 1, acol = (tid & 1) * 4;
    int brow = tid >> 5, bcol = (tid & 31) * 4;
    int tx = (tid & 15) * TN, ty = (tid >> 4) * TM;
    float acc[TM][TN] = {};
    for (int k0 = 0; k0 < K; k0 += BK) {
        int gr = bm + arow;
        #pragma unroll
        for (int i = 0; i < 4; i++)
            As[acol + i][arow] = (gr < M) ? A[(long)gr * lda + k0 + acol + i] : 0.f;
        int gk = k0 + brow;
        #pragma unroll
        for (int i = 0; i < 4; i++) {
            int gn = bn + bcol + i;
            Bs[brow][bcol + i] = (gn < N) ? Bm[(long)gk * ldb + gn] : 0.f;
        }
        __syncthreads();
        #pragma unroll
        for (int kk = 0; kk < BK; kk++) {
            float ar[TM], br[TN];
            #pragma unroll
            for (int i = 0; i < TM; i++) ar[i] = As[kk][ty + i];
            #pragma unroll
            for (int j = 0; j < TN; j++) br[j] = Bs[kk][tx + j];
            #pragma unroll
            for (int i = 0; i < TM; i++)
                #pragma unroll
                for (int j = 0; j < TN; j++)
                    acc[i][j] += ar[i] * br[j];
        }
        __syncthreads();
    }
    #pragma unroll
    for (int i = 0; i < TM; i++) {
        int gm = bm + ty + i;
        if (gm >= M) continue;
        #pragma unroll
        for (int j = 0; j < TN; j++) {
            int gn = bn + tx + j;
            if (gn >= N) continue;
            C[(long)gm * ldc + gn] = acc[i][j];
        }
    }
}

// ---------------- fused QKV (grid.z = 3), with prefetch ----------------
__global__ void __launch_bounds__(256)
gpt_gemm_qkv(const float* __restrict__ A,
             const float* __restrict__ Wq, const float* __restrict__ Wk,
             const float* __restrict__ Wv,
             float* __restrict__ Oq, float* __restrict__ Ok, float* __restrict__ Ov) {
    constexpr int BM = 128, BN = 128, BK = 8, TM = 8, TN = 8;
    __shared__ float As[BK][BM];
    __shared__ float Bs[BK][BN];
    int z = blockIdx.z;
    const float* Bm = (z == 0) ? Wq : (z == 1) ? Wk : Wv;
    float* C = (z == 0) ? Oq : (z == 1) ? Ok : Ov;

    int bm = blockIdx.y * BM, bn = blockIdx.x * BN;
    int tid = threadIdx.x;
    int arow = tid >> 1, acol = (tid & 1) * 4;
    int brow = tid >> 5, bcol = (tid & 31) * 4;
    int tx = (tid & 15) * TN, ty = (tid >> 4) * TM;

    const float* Aptr = A + (long)(bm + arow) * DQ + acol;
    const float* Bptr = Bm + (long)brow * DQ + bn + bcol;
    float4 pa = *(const float4*)Aptr;
    float4 pb = *(const float4*)Bptr;

    float acc[TM][TN] = {};
    for (int k0 = 0; k0 < DQ; k0 += BK) {
        As[acol + 0][arow] = pa.x; As[acol + 1][arow] = pa.y;
        As[acol + 2][arow] = pa.z; As[acol + 3][arow] = pa.w;
        *(float4*)&Bs[brow][bcol] = pb;
        __syncthreads();
        if (k0 + BK < DQ) {
            pa = *(const float4*)(Aptr + k0 + BK);
            pb = *(const float4*)(Bptr + (long)(k0 + BK) * DQ);
        }
        #pragma unroll
        for (int kk = 0; kk < BK; kk++) {
            float ar[TM], br[TN];
            #pragma unroll
            for (int i = 0; i < TM; i++) ar[i] = As[kk][ty + i];
            #pragma unroll
            for (int j = 0; j < TN; j++) br[j] = Bs[kk][tx + j];
            #pragma unroll
            for (int i = 0; i < TM; i++)
                #pragma unroll
                for (int j = 0; j < TN; j++)
                    acc[i][j] += ar[i] * br[j];
        }
        __syncthreads();
    }
    #pragma unroll
    for (int i = 0; i < TM; i++)
        #pragma unroll
        for (int j = 0; j < TN; j++)
            C[(long)(bm + ty + i) * DQ + bn + tx + j] = acc[i][j];
}

// ---------------- fused flash attention ----------------
// grid (8, 48): q-tile (64 queries) x (b*H). 256 threads.
// dynamic smem: Qs[64][64] d-major | Ks[64][64] d-major (reused as P[qr][kc]) |
//               Vs[64][64] kk-major | rowm/rowl/rowf[64]
__global__ void __launch_bounds__(256, 2)
gpt_flash(const float* __restrict__ Q, const float* __restrict__ Kx,
          const float* __restrict__ Vx, float* __restrict__ ctx) {
    extern __shared__ float sm[];
    float* Qs   = sm;            // 4096
    float* Ks   = sm + 4096;     // 4096 (also P)
    float* Vs   = sm + 8192;     // 4096
    float* rowm = sm + 12288;
    float* rowl = rowm + 64;
    float* rowf = rowm + 128;

    int z = blockIdx.y;
    int b = z / HQ, h = z - b * HQ;
    int qt = blockIdx.x, q0 = qt * 64;
    int tid = threadIdx.x;
    int r = tid & 63, dg = tid >> 6;          // loader role
    int ty = tid >> 4, tx = tid & 15;         // compute role

    // load Q tile transposed: Qs[d][qr]
    {
        const float* qrow = Q + ((long)(b * SQ + q0 + r)) * DQ + h * HDQ + dg * 16;
        #pragma unroll
        for (int i = 0; i < 4; i++) {
            float4 t = *(const float4*)(qrow + i * 4);
            int d = dg * 16 + i * 4;
            Qs[(d + 0) * 64 + r] = t.x; Qs[(d + 1) * 64 + r] = t.y;
            Qs[(d + 2) * 64 + r] = t.z; Qs[(d + 3) * 64 + r] = t.w;
        }
    }
    if (tid < 64) { rowm[tid] = -1e30f; rowl[tid] = 0.f; }

    float o[4][4] = {};

    for (int j = 0; j <= qt; j++) {
        int k0 = j * 64;
        __syncthreads();   // protect prior P/Vs reads (and Qs/rowm on first iter)
        {
            const float* krow = Kx + ((long)(b * SQ + k0 + r)) * DQ + h * HDQ + dg * 16;
            const float* vrow = Vx + ((long)(b * SQ + k0 + r)) * DQ + h * HDQ + dg * 16;
            #pragma unroll
            for (int i = 0; i < 4; i++) {
                float4 t = *(const float4*)(krow + i * 4);
                int d = dg * 16 + i * 4;
                Ks[(d + 0) * 64 + r] = t.x; Ks[(d + 1) * 64 + r] = t.y;
                Ks[(d + 2) * 64 + r] = t.z; Ks[(d + 3) * 64 + r] = t.w;
                float4 tv = *(const float4*)(vrow + i * 4);
                *(float4*)&Vs[r * 64 + dg * 16 + i * 4] = tv;
            }
        }
        __syncthreads();

        // S = Q . K^T (per-thread 4x4)
        float s[4][4] = {};
        #pragma unroll 8
        for (int d = 0; d < 64; d++) {
            float qv[4], kv[4];
            #pragma unroll
            for (int i = 0; i < 4; i++) qv[i] = Qs[d * 64 + ty * 4 + i];
            #pragma unroll
            for (int c = 0; c < 4; c++) kv[c] = Ks[d * 64 + tx * 4 + c];
            #pragma unroll
            for (int i = 0; i < 4; i++)
                #pragma unroll
                for (int c = 0; c < 4; c++)
                    s[i][c] += qv[i] * kv[c];
        }
        #pragma unroll
        for (int i = 0; i < 4; i++)
            #pragma unroll
            for (int c = 0; c < 4; c++) {
                s[i][c] *= 0.125f;
                if (j == qt && (k0 + tx * 4 + c) > (q0 + ty * 4 + i)) s[i][c] = -1e30f;
            }
        __syncthreads();   // done reading Ks as K
        // store P-pre into Ks buffer, layout [qr][kc]
        #pragma unroll
        for (int i = 0; i < 4; i++)
            #pragma unroll
            for (int c = 0; c < 4; c++)
                Ks[(ty * 4 + i) * 64 + tx * 4 + c] = s[i][c];
        __syncthreads();

        // online softmax stats (threads 0..63, one row each, rotated scan)
        if (tid < 64) {
            float m_old = rowm[tid], m = m_old;
            #pragma unroll 8
            for (int t = 0; t < 64; t++) {
                int kk = (t + tid) & 63;
                m = fmaxf(m, Ks[tid * 64 + kk]);
            }
            float f = __expf(m_old - m);
            float l = rowl[tid] * f;
            #pragma unroll 8
            for (int t = 0; t < 64; t++) {
                int kk = (t + tid) & 63;
                float p = __expf(Ks[tid * 64 + kk] - m);
                Ks[tid * 64 + kk] = p;
                l += p;
            }
            rowm[tid] = m; rowl[tid] = l; rowf[tid] = f;
        }
        __syncthreads();

        // rescale accumulators + P.V
        float fr[4];
        #pragma unroll
        for (int i = 0; i < 4; i++) fr[i] = rowf[ty * 4 + i];
        #pragma unroll
        for (int i = 0; i < 4; i++)
            #pragma unroll
            for (int c = 0; c < 4; c++) o[i][c] *= fr[i];
        #pragma unroll 8
        for (int kk = 0; kk < 64; kk++) {
            float p[4];
            #pragma unroll
            for (int i = 0; i < 4; i++) p[i] = Ks[(ty * 4 + i) * 64 + kk];
            float4 vv = *(const float4*)&Vs[kk * 64 + tx * 4];
            #pragma unroll
            for (int i = 0; i < 4; i++) {
                o[i][0] += p[i] * vv.x; o[i][1] += p[i] * vv.y;
                o[i][2] += p[i] * vv.z; o[i][3] += p[i] * vv.w;
            }
        }
    }

    // epilogue: normalize and write [b,s,h,hd]
    #pragma unroll
    for (int i = 0; i < 4; i++) {
        float inv = 1.0f / rowl[ty * 4 + i];
        float4 wv = make_float4(o[i][0] * inv, o[i][1] * inv, o[i][2] * inv, o[i][3] * inv);
        *(float4*)(ctx + ((long)(b * SQ + q0 + ty * 4 + i)) * DQ + h * HDQ + tx * 4) = wv;
    }
}

// ---------------- host orchestration ----------------
extern "C" void kernel_launch(void* const* d_in, const int* in_sizes, int n_in,
                              void* d_out, int out_size) {
    const int*   x    = (const int*)  d_in[0];
    const float* tok  = (const float*)d_in[1];
    const float* pos  = (const float*)d_in[2];
    const float* ln1s = (const float*)d_in[3];
    const float* ln1b = (const float*)d_in[4];
    const float* wq   = (const float*)d_in[5];
    const float* wk   = (const float*)d_in[6];
    const float* wv   = (const float*)d_in[7];
    const float* wo   = (const float*)d_in[8];
    const float* bo   = (const float*)d_in[9];
    const float* ln2s = (const float*)d_in[10];
    const float* ln2b = (const float*)d_in[11];
    const float* w1   = (const float*)d_in[12];
    const float* b1   = (const float*)d_in[13];
    const float* w2   = (const float*)d_in[14];
    const float* b2   = (const float*)d_in[15];
    const float* fs   = (const float*)d_in[16];
    const float* fb   = (const float*)d_in[17];
    const float* wout = (const float*)d_in[18];
    float* out = (float*)d_out;

    float *h, *hn, *q, *k, *v, *ctx, *ff;
    cudaGetSymbolAddress((void**)&h,   g_h);
    cudaGetSymbolAddress((void**)&hn,  g_hn);
    cudaGetSymbolAddress((void**)&q,   g_q);
    cudaGetSymbolAddress((void**)&k,   g_k);
    cudaGetSymbolAddress((void**)&v,   g_v);
    cudaGetSymbolAddress((void**)&ctx, g_ctx);
    cudaGetSymbolAddress((void**)&ff,  g_ff);

    const int FLASH_SMEM = (64 * 64 * 3 + 64 * 3) * sizeof(float); // 49920
    cudaFuncSetAttribute(gpt_flash, cudaFuncAttributeMaxDynamicSharedMemorySize, FLASH_SMEM);

    gpt_embed<<<(NT * DQ + 255) / 256, 256>>>(x, tok, pos, h);

    dim3 gQKV(DQ / 128,  NT / 128, 3);     // (6,16,3)
    dim3 gD64(DQ / 128,  NT / 64);         // (6,32)   64-row tiles: proj, ffn2
    dim3 gFF (FFQ / 128, NT / 128);        // (24,16)
    dim3 gFl (SQ / 64,   BQ * HQ);         // (8,48)

    for (int l = 0; l < LQ; l++) {
        const float* Wq = wq + (long)l * DQ * DQ;
        const float* Wk = wk + (long)l * DQ * DQ;
        const float* Wv = wv + (long)l * DQ * DQ;
        const float* Wo = wo + (long)l * DQ * DQ;
        const float* W1 = w1 + (long)l * DQ * FFQ;
        const float* W2 = w2 + (long)l * FFQ * DQ;

        gpt_ln<<<NT, 256>>>(h, ln1s + l * DQ, ln1b + l * DQ, hn);

        gpt_gemm_qkv<<<gQKV, 256>>>(hn, Wq, Wk, Wv, q, k, v);

        gpt_flash<<<gFl, 256, FLASH_SMEM>>>(q, k, v, ctx);

        // h = h + ctx @ Wo + bo
        gpt_gemm_f<2, 64, true><<<gD64, 256>>>(ctx, Wo, bo + l * DQ, h, h,
            NT, DQ, DQ, DQ, DQ, DQ);

        gpt_ln<<<NT, 256>>>(h, ln2s + l * DQ, ln2b + l * DQ, hn);

        // ff = gelu(hn @ W1 + b1)
        gpt_gemm_f<3, 128, true><<<gFF, 256>>>(hn, W1, b1 + l * FFQ, nullptr, ff,
            NT, FFQ, DQ, DQ, FFQ, FFQ);

        // h = h + ff @ W2 + b2
        gpt_gemm_f<2, 64, true><<<gD64, 256>>>(ff, W2, b2 + l * DQ, h, h,
            NT, DQ, FFQ, FFQ, DQ, DQ);
    }

    gpt_ln<<<NT, 256>>>(h, fs, fb, hn);

    // logits = hn @ w_out : fast path on N=50176 (scalar B loads: ldb=50257 is odd),
    // guarded remainder N=81
    const int NFAST = 50176;
    dim3 gVf(NFAST / 128, NT / 128);
    gpt_gemm_f<0, 128, false><<<gVf, 256>>>(hn, wout, nullptr, nullptr, out,
        NT, NFAST, DQ, DQ, VQ, VQ);
    dim3 gVr(1, NT / 128);
    gpt_gemm_g<<<gVr, 256>>>(hn, wout + NFAST, out + NFAST,
        NT, VQ - NFAST, DQ, DQ, VQ, VQ);
}

// round 6
// speedup vs baseline: 2.7260x; 2.0363x over previous
#include <cuda_runtime.h>
#include <cuda_bf16.h>
#include <math.h>
#include <stdint.h>

// ---------------- problem constants ----------------
#define BQ   4
#define SQ   512
#define DQ   768
#define HQ   12
#define HDQ  64
#define LQ   12
#define VQ   50257
#define FFQ  3072
#define NT   (BQ*SQ)   // 2048 tokens

#define ASTR 40        // smem row stride in halves -> 80B rows: 16B-aligned (ldmatrix) + conflict-free

// ---------------- static scratch (no allocs allowed) ----------------
__device__ __align__(128) float g_h  [NT*DQ];
__device__ __align__(128) float g_hn [NT*DQ];
__device__ __align__(128) float g_q  [NT*DQ];
__device__ __align__(128) float g_k  [NT*DQ];
__device__ __align__(128) float g_v  [NT*DQ];
__device__ __align__(128) float g_ctx[NT*DQ];
__device__ __align__(128) float g_ff [NT*FFQ];

// ---------------- helpers ----------------
__device__ __forceinline__ float gelu_f(float x) {
    const float c = 0.7978845608028654f; // sqrt(2/pi)
    float x3 = x * x * x;
    return 0.5f * x * (1.0f + tanhf(c * (x + 0.044715f * x3)));
}

__device__ __forceinline__ uint32_t smem_u32(const void* p) {
    uint32_t a;
    asm("{ .reg .u64 t; cvta.to.shared.u64 t, %1; cvt.u32.u64 %0, t; }" : "=r"(a) : "l"(p));
    return a;
}

// split fp32 pair -> packed hi-bf16x2 / lo-bf16x2
__device__ __forceinline__ void split2(float a, float b, uint32_t& hi, uint32_t& lo) {
    __nv_bfloat16 ha = __float2bfloat16_rn(a), hb = __float2bfloat16_rn(b);
    float ra = a - __bfloat162float(ha), rb = b - __bfloat162float(hb);
    __nv_bfloat16 la = __float2bfloat16_rn(ra), lb = __float2bfloat16_rn(rb);
    hi = ((uint32_t)__bfloat16_as_ushort(hb) << 16) | (uint32_t)__bfloat16_as_ushort(ha);
    lo = ((uint32_t)__bfloat16_as_ushort(lb) << 16) | (uint32_t)__bfloat16_as_ushort(la);
}

__device__ __forceinline__ void ldsm4(uint32_t& r0, uint32_t& r1, uint32_t& r2, uint32_t& r3,
                                      uint32_t addr) {
    asm volatile("ldmatrix.sync.aligned.m8n8.x4.shared.b16 {%0,%1,%2,%3}, [%4];"
        : "=r"(r0), "=r"(r1), "=r"(r2), "=r"(r3) : "r"(addr));
}

__device__ __forceinline__ void mma_bf16(float* c, const uint32_t* a, const uint32_t* b) {
    asm volatile("mma.sync.aligned.m16n8k16.row.col.f32.bf16.bf16.f32 "
        "{%0,%1,%2,%3}, {%4,%5,%6,%7}, {%8,%9}, {%0,%1,%2,%3};"
        : "+f"(c[0]), "+f"(c[1]), "+f"(c[2]), "+f"(c[3])
        : "r"(a[0]), "r"(a[1]), "r"(a[2]), "r"(a[3]), "r"(b[0]), "r"(b[1]));
}

// ---------------- embedding ----------------
__global__ void gpt_embed(const int* __restrict__ x, const float* __restrict__ tok,
                          const float* __restrict__ pos, float* __restrict__ h) {
    int i = blockIdx.x * blockDim.x + threadIdx.x;
    if (i < NT * DQ) {
        int t = i / DQ, d = i - t * DQ;
        int s = t & (SQ - 1);
        h[i] = tok[(long)x[t] * DQ + d] + pos[s * DQ + d];
    }
}

// ---------------- layernorm ----------------
__global__ void gpt_ln(const float* __restrict__ in, const float* __restrict__ scale,
                       const float* __restrict__ shift, float* __restrict__ out) {
    int t = blockIdx.x;
    const float* row = in + (long)t * DQ;
    __shared__ float red[256];
    int tid = threadIdx.x;

    float s = 0.f;
    for (int d = tid; d < DQ; d += 256) s += row[d];
    red[tid] = s; __syncthreads();
    for (int o = 128; o > 0; o >>= 1) { if (tid < o) red[tid] += red[tid + o]; __syncthreads(); }
    float mean = red[0] * (1.0f / DQ); __syncthreads();

    float sq = 0.f;
    for (int d = tid; d < DQ; d += 256) { float v = row[d] - mean; sq += v * v; }
    red[tid] = sq; __syncthreads();
    for (int o = 128; o > 0; o >>= 1) { if (tid < o) red[tid] += red[tid + o]; __syncthreads(); }
    float inv = rsqrtf(red[0] * (1.0f / DQ) + 1e-5f);

    float* orow = out + (long)t * DQ;
    for (int d = tid; d < DQ; d += 256)
        orow[d] = scale[d] * (row[d] - mean) * inv + shift[d];
}

// ---------------- bf16x3 tensor-core GEMM via mma.sync ----------------
// CTA tile 128x128, 8 warps as 2(m) x 4(n), warp tile 64x32.
// K chunked by 32; smem holds hi/lo bf16 of A[128][32] (m,K-major) and
// B^T[128][32] (n,K-major), row stride ASTR halves (80B, 16B-aligned rows).
// EPI: 0 none, 2 +bias+res, 3 gelu(x+bias). NG: guard N (vocab).
template<int EPI, bool NG>
__device__ __forceinline__ void hmma_core(
    const float* __restrict__ A, const float* __restrict__ Bm,
    const float* __restrict__ bias, const float* __restrict__ res,
    float* __restrict__ C, int Ntot, int K, int lda, int ldb, int ldc) {

    __shared__ __align__(16) uint16_t sAh[128 * ASTR], sAl[128 * ASTR];
    __shared__ __align__(16) uint16_t sBh[128 * ASTR], sBl[128 * ASTR];

    int tid = threadIdx.x;
    int lane = tid & 31, wid = tid >> 5;
    int wm = wid >> 2, wn = wid & 3;
    int bm = blockIdx.y * 128, bn = blockIdx.x * 128;

    // loader roles
    int ar  = tid >> 1, acb = (tid & 1) * 16;      // A: row, col-base (16 cols each)
    int bnn = tid & 127, bkg = (tid >> 7) * 16;    // B: n col, k-base (16 ks each)
    bool nok = !NG || (bn + bnn) < Ntot;

    const float* Ap = A + (long)(bm + ar) * lda + acb;
    const float* Bp = Bm + bn + bnn;

    float pa[16], pb[16];
    // prefetch chunk 0
    #pragma unroll
    for (int i = 0; i < 4; i++) {
        float4 t = *(const float4*)(Ap + i * 4);
        pa[i*4+0]=t.x; pa[i*4+1]=t.y; pa[i*4+2]=t.z; pa[i*4+3]=t.w;
    }
    #pragma unroll
    for (int j = 0; j < 16; j++)
        pb[j] = nok ? Bp[(long)(bkg + j) * ldb] : 0.f;

    float acc[4][4][4];
    #pragma unroll
    for (int i = 0; i < 4; i++)
        #pragma unroll
        for (int j = 0; j < 4; j++)
            #pragma unroll
            for (int r2 = 0; r2 < 4; r2++) acc[i][j][r2] = 0.f;

    // ldmatrix lane addressing (computed once)
    int l8 = lane & 7;
    int a_row = ((lane >> 3) & 1) * 8 + l8;   // row offset within 16
    int a_kof = (lane >> 4) * 8;              // k offset within 16
    int b_nof = (lane >> 4) * 8 + l8;         // n offset within 16
    int b_kof = ((lane >> 3) & 1) * 8;

    const int NCH = K >> 5;
    for (int c = 0; c < NCH; c++) {
        if (c) __syncthreads();
        // split & store current chunk
        #pragma unroll
        for (int j = 0; j < 8; j++) {
            uint32_t h, l;
            split2(pa[2*j], pa[2*j+1], h, l);
            *(uint32_t*)&sAh[ar * ASTR + acb + 2*j] = h;
            *(uint32_t*)&sAl[ar * ASTR + acb + 2*j] = l;
        }
        #pragma unroll
        for (int j = 0; j < 8; j++) {
            uint32_t h, l;
            split2(pb[2*j], pb[2*j+1], h, l);
            *(uint32_t*)&sBh[bnn * ASTR + bkg + 2*j] = h;
            *(uint32_t*)&sBl[bnn * ASTR + bkg + 2*j] = l;
        }
        __syncthreads();
        // prefetch next chunk (loads in flight during MMA phase)
        if (c + 1 < NCH) {
            int ko = (c + 1) * 32;
            #pragma unroll
            for (int i = 0; i < 4; i++) {
                float4 t = *(const float4*)(Ap + ko + i * 4);
                pa[i*4+0]=t.x; pa[i*4+1]=t.y; pa[i*4+2]=t.z; pa[i*4+3]=t.w;
            }
            #pragma unroll
            for (int j = 0; j < 16; j++)
                pb[j] = nok ? Bp[(long)(ko + bkg + j) * ldb] : 0.f;
        }
        // MMA phase: 2 k16 steps
        #pragma unroll
        for (int kk = 0; kk < 32; kk += 16) {
            uint32_t fah[4][4], fal[4][4], fbh[4][2], fbl[4][2];
            #pragma unroll
            for (int ma = 0; ma < 4; ma++) {
                int ro = (wm * 64 + ma * 16 + a_row) * ASTR + kk + a_kof;
                ldsm4(fah[ma][0], fah[ma][1], fah[ma][2], fah[ma][3], smem_u32(&sAh[ro]));
                ldsm4(fal[ma][0], fal[ma][1], fal[ma][2], fal[ma][3], smem_u32(&sAl[ro]));
            }
            #pragma unroll
            for (int np = 0; np < 2; np++) {
                int ro = (wn * 32 + np * 16 + b_nof) * ASTR + kk + b_kof;
                ldsm4(fbh[2*np][0], fbh[2*np][1], fbh[2*np+1][0], fbh[2*np+1][1],
                      smem_u32(&sBh[ro]));
                ldsm4(fbl[2*np][0], fbl[2*np][1], fbl[2*np+1][0], fbl[2*np+1][1],
                      smem_u32(&sBl[ro]));
            }
            #pragma unroll
            for (int ma = 0; ma < 4; ma++)
                #pragma unroll
                for (int na = 0; na < 4; na++)
                    mma_bf16(acc[ma][na], fah[ma], fbh[na]);
            #pragma unroll
            for (int ma = 0; ma < 4; ma++)
                #pragma unroll
                for (int na = 0; na < 4; na++)
                    mma_bf16(acc[ma][na], fah[ma], fbl[na]);
            #pragma unroll
            for (int ma = 0; ma < 4; ma++)
                #pragma unroll
                for (int na = 0; na < 4; na++)
                    mma_bf16(acc[ma][na], fal[ma], fbh[na]);
        }
    }

    // epilogue: direct register -> gmem
    int g = lane >> 2, tig = lane & 3;
    #pragma unroll
    for (int ma = 0; ma < 4; ma++) {
        int r0 = bm + wm * 64 + ma * 16 + g;
        #pragma unroll
        for (int na = 0; na < 4; na++) {
            int gn = bn + wn * 32 + na * 8 + 2 * tig;
            #pragma unroll
            for (int half = 0; half < 2; half++) {
                int gm = r0 + half * 8;
                float v0 = acc[ma][na][half * 2 + 0];
                float v1 = acc[ma][na][half * 2 + 1];
                long gi = (long)gm * ldc + gn;
                if (NG) {
                    if (gn < Ntot)     C[gi]     = v0;   // EPI==0 for NG path
                    if (gn + 1 < Ntot) C[gi + 1] = v1;
                } else {
                    if (EPI == 2) {
                        v0 += bias[gn]     + res[gi];
                        v1 += bias[gn + 1] + res[gi + 1];
                    } else if (EPI == 3) {
                        v0 = gelu_f(v0 + bias[gn]);
                        v1 = gelu_f(v1 + bias[gn + 1]);
                    }
                    *(float2*)&C[gi] = make_float2(v0, v1);
                }
            }
        }
    }
}

template<int EPI, bool NG>
__global__ void __launch_bounds__(256, 1)
gpt_hmma(const float* __restrict__ A, const float* __restrict__ Bm,
         const float* __restrict__ bias, const float* __restrict__ res,
         float* __restrict__ C, int Ntot, int K, int lda, int ldb, int ldc) {
    hmma_core<EPI, NG>(A, Bm, bias, res, C, Ntot, K, lda, ldb, ldc);
}

__global__ void __launch_bounds__(256, 1)
gpt_hmma_qkv(const float* __restrict__ A,
             const float* __restrict__ Wq, const float* __restrict__ Wk,
             const float* __restrict__ Wv,
             float* __restrict__ Oq, float* __restrict__ Ok, float* __restrict__ Ov) {
    int z = blockIdx.z;
    const float* B = (z == 0) ? Wq : (z == 1) ? Wk : Wv;
    float* C = (z == 0) ? Oq : (z == 1) ? Ok : Ov;
    hmma_core<0, false>(A, B, nullptr, nullptr, C, DQ, DQ, DQ, DQ, DQ);
}

// ---------------- fused flash attention (unchanged, passing version) ----------------
__global__ void __launch_bounds__(256, 2)
gpt_flash(const float* __restrict__ Q, const float* __restrict__ Kx,
          const float* __restrict__ Vx, float* __restrict__ ctx) {
    extern __shared__ float sm[];
    float* Qs   = sm;
    float* Ks   = sm + 4096;
    float* Vs   = sm + 8192;
    float* rowm = sm + 12288;
    float* rowl = rowm + 64;
    float* rowf = rowm + 128;

    int z = blockIdx.y;
    int b = z / HQ, h = z - b * HQ;
    int qt = blockIdx.x, q0 = qt * 64;
    int tid = threadIdx.x;
    int r = tid & 63, dg = tid >> 6;
    int ty = tid >> 4, tx = tid & 15;

    {
        const float* qrow = Q + ((long)(b * SQ + q0 + r)) * DQ + h * HDQ + dg * 16;
        #pragma unroll
        for (int i = 0; i < 4; i++) {
            float4 t = *(const float4*)(qrow + i * 4);
            int d = dg * 16 + i * 4;
            Qs[(d + 0) * 64 + r] = t.x; Qs[(d + 1) * 64 + r] = t.y;
            Qs[(d + 2) * 64 + r] = t.z; Qs[(d + 3) * 64 + r] = t.w;
        }
    }
    if (tid < 64) { rowm[tid] = -1e30f; rowl[tid] = 0.f; }

    float o[4][4] = {};

    for (int j = 0; j <= qt; j++) {
        int k0 = j * 64;
        __syncthreads();
        {
            const float* krow = Kx + ((long)(b * SQ + k0 + r)) * DQ + h * HDQ + dg * 16;
            const float* vrow = Vx + ((long)(b * SQ + k0 + r)) * DQ + h * HDQ + dg * 16;
            #pragma unroll
            for (int i = 0; i < 4; i++) {
                float4 t = *(const float4*)(krow + i * 4);
                int d = dg * 16 + i * 4;
                Ks[(d + 0) * 64 + r] = t.x; Ks[(d + 1) * 64 + r] = t.y;
                Ks[(d + 2) * 64 + r] = t.z; Ks[(d + 3) * 64 + r] = t.w;
                float4 tv = *(const float4*)(vrow + i * 4);
                *(float4*)&Vs[r * 64 + dg * 16 + i * 4] = tv;
            }
        }
        __syncthreads();

        float s[4][4] = {};
        #pragma unroll 8
        for (int d = 0; d < 64; d++) {
            float qv[4], kv[4];
            #pragma unroll
            for (int i = 0; i < 4; i++) qv[i] = Qs[d * 64 + ty * 4 + i];
            #pragma unroll
            for (int c = 0; c < 4; c++) kv[c] = Ks[d * 64 + tx * 4 + c];
            #pragma unroll
            for (int i = 0; i < 4; i++)
                #pragma unroll
                for (int c = 0; c < 4; c++)
                    s[i][c] += qv[i] * kv[c];
        }
        #pragma unroll
        for (int i = 0; i < 4; i++)
            #pragma unroll
            for (int c = 0; c < 4; c++) {
                s[i][c] *= 0.125f;
                if (j == qt && (k0 + tx * 4 + c) > (q0 + ty * 4 + i)) s[i][c] = -1e30f;
            }
        __syncthreads();
        #pragma unroll
        for (int i = 0; i < 4; i++)
            #pragma unroll
            for (int c = 0; c < 4; c++)
                Ks[(ty * 4 + i) * 64 + tx * 4 + c] = s[i][c];
        __syncthreads();

        if (tid < 64) {
            float m_old = rowm[tid], m = m_old;
            #pragma unroll 8
            for (int t = 0; t < 64; t++) {
                int kk = (t + tid) & 63;
                m = fmaxf(m, Ks[tid * 64 + kk]);
            }
            float f = __expf(m_old - m);
            float l = rowl[tid] * f;
            #pragma unroll 8
            for (int t = 0; t < 64; t++) {
                int kk = (t + tid) & 63;
                float p = __expf(Ks[tid * 64 + kk] - m);
                Ks[tid * 64 + kk] = p;
                l += p;
            }
            rowm[tid] = m; rowl[tid] = l; rowf[tid] = f;
        }
        __syncthreads();

        float fr[4];
        #pragma unroll
        for (int i = 0; i < 4; i++) fr[i] = rowf[ty * 4 + i];
        #pragma unroll
        for (int i = 0; i < 4; i++)
            #pragma unroll
            for (int c = 0; c < 4; c++) o[i][c] *= fr[i];
        #pragma unroll 8
        for (int kk = 0; kk < 64; kk++) {
            float p[4];
            #pragma unroll
            for (int i = 0; i < 4; i++) p[i] = Ks[(ty * 4 + i) * 64 + kk];
            float4 vv = *(const float4*)&Vs[kk * 64 + tx * 4];
            #pragma unroll
            for (int i = 0; i < 4; i++) {
                o[i][0] += p[i] * vv.x; o[i][1] += p[i] * vv.y;
                o[i][2] += p[i] * vv.z; o[i][3] += p[i] * vv.w;
            }
        }
    }

    #pragma unroll
    for (int i = 0; i < 4; i++) {
        float inv = 1.0f / rowl[ty * 4 + i];
        float4 wv = make_float4(o[i][0] * inv, o[i][1] * inv, o[i][2] * inv, o[i][3] * inv);
        *(float4*)(ctx + ((long)(b * SQ + q0 + ty * 4 + i)) * DQ + h * HDQ + tx * 4) = wv;
    }
}

// ---------------- host orchestration ----------------
extern "C" void kernel_launch(void* const* d_in, const int* in_sizes, int n_in,
                              void* d_out, int out_size) {
    const int*   x    = (const int*)  d_in[0];
    const float* tok  = (const float*)d_in[1];
    const float* pos  = (const float*)d_in[2];
    const float* ln1s = (const float*)d_in[3];
    const float* ln1b = (const float*)d_in[4];
    const float* wq   = (const float*)d_in[5];
    const float* wk   = (const float*)d_in[6];
    const float* wv   = (const float*)d_in[7];
    const float* wo   = (const float*)d_in[8];
    const float* bo   = (const float*)d_in[9];
    const float* ln2s = (const float*)d_in[10];
    const float* ln2b = (const float*)d_in[11];
    const float* w1   = (const float*)d_in[12];
    const float* b1   = (const float*)d_in[13];
    const float* w2   = (const float*)d_in[14];
    const float* b2   = (const float*)d_in[15];
    const float* fs   = (const float*)d_in[16];
    const float* fb   = (const float*)d_in[17];
    const float* wout = (const float*)d_in[18];
    float* out = (float*)d_out;

    float *h, *hn, *q, *k, *v, *ctx, *ff;
    cudaGetSymbolAddress((void**)&h,   g_h);
    cudaGetSymbolAddress((void**)&hn,  g_hn);
    cudaGetSymbolAddress((void**)&q,   g_q);
    cudaGetSymbolAddress((void**)&k,   g_k);
    cudaGetSymbolAddress((void**)&v,   g_v);
    cudaGetSymbolAddress((void**)&ctx, g_ctx);
    cudaGetSymbolAddress((void**)&ff,  g_ff);

    const int FLASH_SMEM = (64 * 64 * 3 + 64 * 3) * sizeof(float); // 49920
    cudaFuncSetAttribute(gpt_flash, cudaFuncAttributeMaxDynamicSharedMemorySize, FLASH_SMEM);

    gpt_embed<<<(NT * DQ + 255) / 256, 256>>>(x, tok, pos, h);

    dim3 gP (DQ / 128,  NT / 128);        // (6,16)
    dim3 gQ (DQ / 128,  NT / 128, 3);     // (6,16,3)
    dim3 gF1(FFQ / 128, NT / 128);        // (24,16)
    dim3 gV ((VQ + 127) / 128, NT / 128); // (393,16)
    dim3 gFl(SQ / 64,   BQ * HQ);         // (8,48)

    for (int l = 0; l < LQ; l++) {
        const float* Wq = wq + (long)l * DQ * DQ;
        const float* Wk = wk + (long)l * DQ * DQ;
        const float* Wv = wv + (long)l * DQ * DQ;
        const float* Wo = wo + (long)l * DQ * DQ;
        const float* W1 = w1 + (long)l * DQ * FFQ;
        const float* W2 = w2 + (long)l * FFQ * DQ;

        gpt_ln<<<NT, 256>>>(h, ln1s + l * DQ, ln1b + l * DQ, hn);

        gpt_hmma_qkv<<<gQ, 256>>>(hn, Wq, Wk, Wv, q, k, v);

        gpt_flash<<<gFl, 256, FLASH_SMEM>>>(q, k, v, ctx);

        // h = h + ctx @ Wo + bo
        gpt_hmma<2, false><<<gP, 256>>>(ctx, Wo, bo + l * DQ, h, h,
            DQ, DQ, DQ, DQ, DQ);

        gpt_ln<<<NT, 256>>>(h, ln2s + l * DQ, ln2b + l * DQ, hn);

        // ff = gelu(hn @ W1 + b1)
        gpt_hmma<3, false><<<gF1, 256>>>(hn, W1, b1 + l * FFQ, nullptr, ff,
            FFQ, DQ, DQ, FFQ, FFQ);

        // h = h + ff @ W2 + b2
        gpt_hmma<2, false><<<gP, 256>>>(ff, W2, b2 + l * DQ, h, h,
            DQ, FFQ, FFQ, DQ, DQ);
    }

    gpt_ln<<<NT, 256>>>(h, fs, fb, hn);

    // logits = hn @ w_out : guarded N=50257
    gpt_hmma<0, true><<<gV, 256>>>(hn, wout, nullptr, nullptr, out,
        VQ, DQ, DQ, VQ, VQ);
}

// round 7
// speedup vs baseline: 2.7295x; 1.0013x over previous
#include <cuda_runtime.h>
#include <cuda_bf16.h>
#include <math.h>
#include <stdint.h>

// ---------------- problem constants ----------------
#define BQ   4
#define SQ   512
#define DQ   768
#define HQ   12
#define HDQ  64
#define LQ   12
#define VQ   50257
#define FFQ  3072
#define NT   (BQ*SQ)   // 2048 tokens

#define ASTR 40        // smem row stride in halves -> 80B rows: 16B-aligned (ldmatrix) + conflict-free

// ---------------- static scratch (no allocs allowed) ----------------
__device__ __align__(128) float g_h  [NT*DQ];
__device__ __align__(128) float g_hn [NT*DQ];
__device__ __align__(128) float g_q  [NT*DQ];
__device__ __align__(128) float g_k  [NT*DQ];
__device__ __align__(128) float g_v  [NT*DQ];
__device__ __align__(128) float g_ctx[NT*DQ];
__device__ __align__(128) float g_ff [NT*FFQ];

// ---------------- helpers ----------------
__device__ __forceinline__ float gelu_f(float x) {
    const float c = 0.7978845608028654f; // sqrt(2/pi)
    float x3 = x * x * x;
    return 0.5f * x * (1.0f + tanhf(c * (x + 0.044715f * x3)));
}

__device__ __forceinline__ uint32_t smem_u32(const void* p) {
    uint32_t a;
    asm("{ .reg .u64 t; cvta.to.shared.u64 t, %1; cvt.u32.u64 %0, t; }" : "=r"(a) : "l"(p));
    return a;
}

// split fp32 pair -> packed hi-bf16x2 / lo-bf16x2
__device__ __forceinline__ void split2(float a, float b, uint32_t& hi, uint32_t& lo) {
    __nv_bfloat16 ha = __float2bfloat16_rn(a), hb = __float2bfloat16_rn(b);
    float ra = a - __bfloat162float(ha), rb = b - __bfloat162float(hb);
    __nv_bfloat16 la = __float2bfloat16_rn(ra), lb = __float2bfloat16_rn(rb);
    hi = ((uint32_t)__bfloat16_as_ushort(hb) << 16) | (uint32_t)__bfloat16_as_ushort(ha);
    lo = ((uint32_t)__bfloat16_as_ushort(lb) << 16) | (uint32_t)__bfloat16_as_ushort(la);
}

__device__ __forceinline__ void ldsm4(uint32_t& r0, uint32_t& r1, uint32_t& r2, uint32_t& r3,
                                      uint32_t addr) {
    asm volatile("ldmatrix.sync.aligned.m8n8.x4.shared.b16 {%0,%1,%2,%3}, [%4];"
        : "=r"(r0), "=r"(r1), "=r"(r2), "=r"(r3) : "r"(addr));
}

__device__ __forceinline__ void mma_bf16(float* c, const uint32_t* a, const uint32_t* b) {
    asm volatile("mma.sync.aligned.m16n8k16.row.col.f32.bf16.bf16.f32 "
        "{%0,%1,%2,%3}, {%4,%5,%6,%7}, {%8,%9}, {%0,%1,%2,%3};"
        : "+f"(c[0]), "+f"(c[1]), "+f"(c[2]), "+f"(c[3])
        : "r"(a[0]), "r"(a[1]), "r"(a[2]), "r"(a[3]), "r"(b[0]), "r"(b[1]));
}

// ---------------- embedding ----------------
__global__ void gpt_embed(const int* __restrict__ x, const float* __restrict__ tok,
                          const float* __restrict__ pos, float* __restrict__ h) {
    int i = blockIdx.x * blockDim.x + threadIdx.x;
    if (i < NT * DQ) {
        int t = i / DQ, d = i - t * DQ;
        int s = t & (SQ - 1);
        h[i] = tok[(long)x[t] * DQ + d] + pos[s * DQ + d];
    }
}

// ---------------- layernorm ----------------
__global__ void gpt_ln(const float* __restrict__ in, const float* __restrict__ scale,
                       const float* __restrict__ shift, float* __restrict__ out) {
    int t = blockIdx.x;
    const float* row = in + (long)t * DQ;
    __shared__ float red[256];
    int tid = threadIdx.x;

    float s = 0.f;
    for (int d = tid; d < DQ; d += 256) s += row[d];
    red[tid] = s; __syncthreads();
    for (int o = 128; o > 0; o >>= 1) { if (tid < o) red[tid] += red[tid + o]; __syncthreads(); }
    float mean = red[0] * (1.0f / DQ); __syncthreads();

    float sq = 0.f;
    for (int d = tid; d < DQ; d += 256) { float v = row[d] - mean; sq += v * v; }
    red[tid] = sq; __syncthreads();
    for (int o = 128; o > 0; o >>= 1) { if (tid < o) red[tid] += red[tid + o]; __syncthreads(); }
    float inv = rsqrtf(red[0] * (1.0f / DQ) + 1e-5f);

    float* orow = out + (long)t * DQ;
    for (int d = tid; d < DQ; d += 256)
        orow[d] = scale[d] * (row[d] - mean) * inv + shift[d];
}

// ---------------- bf16x3 tensor-core GEMM via mma.sync ----------------
// CTA tile 128x128, 8 warps as 2(m) x 4(n), warp tile 64x32.
// K chunked by 32; smem holds hi/lo bf16 of A[128][32] (m,K-major) and
// B^T[128][32] (n,K-major), row stride ASTR halves (80B, 16B-aligned rows).
// EPI: 0 none, 2 +bias+res, 3 gelu(x+bias). NG: guard N (vocab).
template<int EPI, bool NG>
__device__ __forceinline__ void hmma_core(
    const float* __restrict__ A, const float* __restrict__ Bm,
    const float* __restrict__ bias, const float* __restrict__ res,
    float* __restrict__ C, int Ntot, int K, int lda, int ldb, int ldc) {

    __shared__ __align__(16) uint16_t sAh[128 * ASTR], sAl[128 * ASTR];
    __shared__ __align__(16) uint16_t sBh[128 * ASTR], sBl[128 * ASTR];

    int tid = threadIdx.x;
    int lane = tid & 31, wid = tid >> 5;
    int wm = wid >> 2, wn = wid & 3;
    int bm = blockIdx.y * 128, bn = blockIdx.x * 128;

    // loader roles
    int ar  = tid >> 1, acb = (tid & 1) * 16;      // A: row, col-base (16 cols each)
    int bnn = tid & 127, bkg = (tid >> 7) * 16;    // B: n col, k-base (16 ks each)
    bool nok = !NG || (bn + bnn) < Ntot;

    const float* Ap = A + (long)(bm + ar) * lda + acb;
    const float* Bp = Bm + bn + bnn;

    float pa[16], pb[16];
    // prefetch chunk 0
    #pragma unroll
    for (int i = 0; i < 4; i++) {
        float4 t = *(const float4*)(Ap + i * 4);
        pa[i*4+0]=t.x; pa[i*4+1]=t.y; pa[i*4+2]=t.z; pa[i*4+3]=t.w;
    }
    #pragma unroll
    for (int j = 0; j < 16; j++)
        pb[j] = nok ? Bp[(long)(bkg + j) * ldb] : 0.f;

    float acc[4][4][4];
    #pragma unroll
    for (int i = 0; i < 4; i++)
        #pragma unroll
        for (int j = 0; j < 4; j++)
            #pragma unroll
            for (int r2 = 0; r2 < 4; r2++) acc[i][j][r2] = 0.f;

    // ldmatrix lane addressing (computed once)
    int l8 = lane & 7;
    int a_row = ((lane >> 3) & 1) * 8 + l8;   // row offset within 16
    int a_kof = (lane >> 4) * 8;              // k offset within 16
    int b_nof = (lane >> 4) * 8 + l8;         // n offset within 16
    int b_kof = ((lane >> 3) & 1) * 8;

    const int NCH = K >> 5;
    for (int c = 0; c < NCH; c++) {
        if (c) __syncthreads();
        // split & store current chunk
        #pragma unroll
        for (int j = 0; j < 8; j++) {
            uint32_t h, l;
            split2(pa[2*j], pa[2*j+1], h, l);
            *(uint32_t*)&sAh[ar * ASTR + acb + 2*j] = h;
            *(uint32_t*)&sAl[ar * ASTR + acb + 2*j] = l;
        }
        #pragma unroll
        for (int j = 0; j < 8; j++) {
            uint32_t h, l;
            split2(pb[2*j], pb[2*j+1], h, l);
            *(uint32_t*)&sBh[bnn * ASTR + bkg + 2*j] = h;
            *(uint32_t*)&sBl[bnn * ASTR + bkg + 2*j] = l;
        }
        __syncthreads();
        // prefetch next chunk (loads in flight during MMA phase)
        if (c + 1 < NCH) {
            int ko = (c + 1) * 32;
            #pragma unroll
            for (int i = 0; i < 4; i++) {
                float4 t = *(const float4*)(Ap + ko + i * 4);
                pa[i*4+0]=t.x; pa[i*4+1]=t.y; pa[i*4+2]=t.z; pa[i*4+3]=t.w;
            }
            #pragma unroll
            for (int j = 0; j < 16; j++)
                pb[j] = nok ? Bp[(long)(ko + bkg + j) * ldb] : 0.f;
        }
        // MMA phase: 2 k16 steps
        #pragma unroll
        for (int kk = 0; kk < 32; kk += 16) {
            uint32_t fah[4][4], fal[4][4], fbh[4][2], fbl[4][2];
            #pragma unroll
            for (int ma = 0; ma < 4; ma++) {
                int ro = (wm * 64 + ma * 16 + a_row) * ASTR + kk + a_kof;
                ldsm4(fah[ma][0], fah[ma][1], fah[ma][2], fah[ma][3], smem_u32(&sAh[ro]));
                ldsm4(fal[ma][0], fal[ma][1], fal[ma][2], fal[ma][3], smem_u32(&sAl[ro]));
            }
            #pragma unroll
            for (int np = 0; np < 2; np++) {
                int ro = (wn * 32 + np * 16 + b_nof) * ASTR + kk + b_kof;
                ldsm4(fbh[2*np][0], fbh[2*np][1], fbh[2*np+1][0], fbh[2*np+1][1],
                      smem_u32(&sBh[ro]));
                ldsm4(fbl[2*np][0], fbl[2*np][1], fbl[2*np+1][0], fbl[2*np+1][1],
                      smem_u32(&sBl[ro]));
            }
            #pragma unroll
            for (int ma = 0; ma < 4; ma++)
                #pragma unroll
                for (int na = 0; na < 4; na++)
                    mma_bf16(acc[ma][na], fah[ma], fbh[na]);
            #pragma unroll
            for (int ma = 0; ma < 4; ma++)
                #pragma unroll
                for (int na = 0; na < 4; na++)
                    mma_bf16(acc[ma][na], fah[ma], fbl[na]);
            #pragma unroll
            for (int ma = 0; ma < 4; ma++)
                #pragma unroll
                for (int na = 0; na < 4; na++)
                    mma_bf16(acc[ma][na], fal[ma], fbh[na]);
        }
    }

    // epilogue: direct register -> gmem
    int g = lane >> 2, tig = lane & 3;
    #pragma unroll
    for (int ma = 0; ma < 4; ma++) {
        int r0 = bm + wm * 64 + ma * 16 + g;
        #pragma unroll
        for (int na = 0; na < 4; na++) {
            int gn = bn + wn * 32 + na * 8 + 2 * tig;
            #pragma unroll
            for (int half = 0; half < 2; half++) {
                int gm = r0 + half * 8;
                float v0 = acc[ma][na][half * 2 + 0];
                float v1 = acc[ma][na][half * 2 + 1];
                long gi = (long)gm * ldc + gn;
                if (NG) {
                    if (gn < Ntot)     C[gi]     = v0;   // EPI==0 for NG path
                    if (gn + 1 < Ntot) C[gi + 1] = v1;
                } else {
                    if (EPI == 2) {
                        v0 += bias[gn]     + res[gi];
                        v1 += bias[gn + 1] + res[gi + 1];
                    } else if (EPI == 3) {
                        v0 = gelu_f(v0 + bias[gn]);
                        v1 = gelu_f(v1 + bias[gn + 1]);
                    }
                    *(float2*)&C[gi] = make_float2(v0, v1);
                }
            }
        }
    }
}

template<int EPI, bool NG>
__global__ void __launch_bounds__(256, 1)
gpt_hmma(const float* __restrict__ A, const float* __restrict__ Bm,
         const float* __restrict__ bias, const float* __restrict__ res,
         float* __restrict__ C, int Ntot, int K, int lda, int ldb, int ldc) {
    hmma_core<EPI, NG>(A, Bm, bias, res, C, Ntot, K, lda, ldb, ldc);
}

__global__ void __launch_bounds__(256, 1)
gpt_hmma_qkv(const float* __restrict__ A,
             const float* __restrict__ Wq, const float* __restrict__ Wk,
             const float* __restrict__ Wv,
             float* __restrict__ Oq, float* __restrict__ Ok, float* __restrict__ Ov) {
    int z = blockIdx.z;
    const float* B = (z == 0) ? Wq : (z == 1) ? Wk : Wv;
    float* C = (z == 0) ? Oq : (z == 1) ? Ok : Ov;
    hmma_core<0, false>(A, B, nullptr, nullptr, C, DQ, DQ, DQ, DQ, DQ);
}

// ---------------- fused flash attention (unchanged, passing version) ----------------
__global__ void __launch_bounds__(256, 2)
gpt_flash(const float* __restrict__ Q, const float* __restrict__ Kx,
          const float* __restrict__ Vx, float* __restrict__ ctx) {
    extern __shared__ float sm[];
    float* Qs   = sm;
    float* Ks   = sm + 4096;
    float* Vs   = sm + 8192;
    float* rowm = sm + 12288;
    float* rowl = rowm + 64;
    float* rowf = rowm + 128;

    int z = blockIdx.y;
    int b = z / HQ, h = z - b * HQ;
    int qt = blockIdx.x, q0 = qt * 64;
    int tid = threadIdx.x;
    int r = tid & 63, dg = tid >> 6;
    int ty = tid >> 4, tx = tid & 15;

    {
        const float* qrow = Q + ((long)(b * SQ + q0 + r)) * DQ + h * HDQ + dg * 16;
        #pragma unroll
        for (int i = 0; i < 4; i++) {
            float4 t = *(const float4*)(qrow + i * 4);
            int d = dg * 16 + i * 4;
            Qs[(d + 0) * 64 + r] = t.x; Qs[(d + 1) * 64 + r] = t.y;
            Qs[(d + 2) * 64 + r] = t.z; Qs[(d + 3) * 64 + r] = t.w;
        }
    }
    if (tid < 64) { rowm[tid] = -1e30f; rowl[tid] = 0.f; }

    float o[4][4] = {};

    for (int j = 0; j <= qt; j++) {
        int k0 = j * 64;
        __syncthreads();
        {
            const float* krow = Kx + ((long)(b * SQ + k0 + r)) * DQ + h * HDQ + dg * 16;
            const float* vrow = Vx + ((long)(b * SQ + k0 + r)) * DQ + h * HDQ + dg * 16;
            #pragma unroll
            for (int i = 0; i < 4; i++) {
                float4 t = *(const float4*)(krow + i * 4);
                int d = dg * 16 + i * 4;
                Ks[(d + 0) * 64 + r] = t.x; Ks[(d + 1) * 64 + r] = t.y;
                Ks[(d + 2) * 64 + r] = t.z; Ks[(d + 3) * 64 + r] = t.w;
                float4 tv = *(const float4*)(vrow + i * 4);
                *(float4*)&Vs[r * 64 + dg * 16 + i * 4] = tv;
            }
        }
        __syncthreads();

        float s[4][4] = {};
        #pragma unroll 8
        for (int d = 0; d < 64; d++) {
            float qv[4], kv[4];
            #pragma unroll
            for (int i = 0; i < 4; i++) qv[i] = Qs[d * 64 + ty * 4 + i];
            #pragma unroll
            for (int c = 0; c < 4; c++) kv[c] = Ks[d * 64 + tx * 4 + c];
            #pragma unroll
            for (int i = 0; i < 4; i++)
                #pragma unroll
                for (int c = 0; c < 4; c++)
                    s[i][c] += qv[i] * kv[c];
        }
        #pragma unroll
        for (int i = 0; i < 4; i++)
            #pragma unroll
            for (int c = 0; c < 4; c++) {
                s[i][c] *= 0.125f;
                if (j == qt && (k0 + tx * 4 + c) > (q0 + ty * 4 + i)) s[i][c] = -1e30f;
            }
        __syncthreads();
        #pragma unroll
        for (int i = 0; i < 4; i++)
            #pragma unroll
            for (int c = 0; c < 4; c++)
                Ks[(ty * 4 + i) * 64 + tx * 4 + c] = s[i][c];
        __syncthreads();

        if (tid < 64) {
            float m_old = rowm[tid], m = m_old;
            #pragma unroll 8
            for (int t = 0; t < 64; t++) {
                int kk = (t + tid) & 63;
                m = fmaxf(m, Ks[tid * 64 + kk]);
            }
            float f = __expf(m_old - m);
            float l = rowl[tid] * f;
            #pragma unroll 8
            for (int t = 0; t < 64; t++) {
                int kk = (t + tid) & 63;
                float p = __expf(Ks[tid * 64 + kk] - m);
                Ks[tid * 64 + kk] = p;
                l += p;
            }
            rowm[tid] = m; rowl[tid] = l; rowf[tid] = f;
        }
        __syncthreads();

        float fr[4];
        #pragma unroll
        for (int i = 0; i < 4; i++) fr[i] = rowf[ty * 4 + i];
        #pragma unroll
        for (int i = 0; i < 4; i++)
            #pragma unroll
            for (int c = 0; c < 4; c++) o[i][c] *= fr[i];
        #pragma unroll 8
        for (int kk = 0; kk < 64; kk++) {
            float p[4];
            #pragma unroll
            for (int i = 0; i < 4; i++) p[i] = Ks[(ty * 4 + i) * 64 + kk];
            float4 vv = *(const float4*)&Vs[kk * 64 + tx * 4];
            #pragma unroll
            for (int i = 0; i < 4; i++) {
                o[i][0] += p[i] * vv.x; o[i][1] += p[i] * vv.y;
                o[i][2] += p[i] * vv.z; o[i][3] += p[i] * vv.w;
            }
        }
    }

    #pragma unroll
    for (int i = 0; i < 4; i++) {
        float inv = 1.0f / rowl[ty * 4 + i];
        float4 wv = make_float4(o[i][0] * inv, o[i][1] * inv, o[i][2] * inv, o[i][3] * inv);
        *(float4*)(ctx + ((long)(b * SQ + q0 + ty * 4 + i)) * DQ + h * HDQ + tx * 4) = wv;
    }
}

// ---------------- host orchestration ----------------
extern "C" void kernel_launch(void* const* d_in, const int* in_sizes, int n_in,
                              void* d_out, int out_size) {
    const int*   x    = (const int*)  d_in[0];
    const float* tok  = (const float*)d_in[1];
    const float* pos  = (const float*)d_in[2];
    const float* ln1s = (const float*)d_in[3];
    const float* ln1b = (const float*)d_in[4];
    const float* wq   = (const float*)d_in[5];
    const float* wk   = (const float*)d_in[6];
    const float* wv   = (const float*)d_in[7];
    const float* wo   = (const float*)d_in[8];
    const float* bo   = (const float*)d_in[9];
    const float* ln2s = (const float*)d_in[10];
    const float* ln2b = (const float*)d_in[11];
    const float* w1   = (const float*)d_in[12];
    const float* b1   = (const float*)d_in[13];
    const float* w2   = (const float*)d_in[14];
    const float* b2   = (const float*)d_in[15];
    const float* fs   = (const float*)d_in[16];
    const float* fb   = (const float*)d_in[17];
    const float* wout = (const float*)d_in[18];
    float* out = (float*)d_out;

    float *h, *hn, *q, *k, *v, *ctx, *ff;
    cudaGetSymbolAddress((void**)&h,   g_h);
    cudaGetSymbolAddress((void**)&hn,  g_hn);
    cudaGetSymbolAddress((void**)&q,   g_q);
    cudaGetSymbolAddress((void**)&k,   g_k);
    cudaGetSymbolAddress((void**)&v,   g_v);
    cudaGetSymbolAddress((void**)&ctx, g_ctx);
    cudaGetSymbolAddress((void**)&ff,  g_ff);

    const int FLASH_SMEM = (64 * 64 * 3 + 64 * 3) * sizeof(float); // 49920
    cudaFuncSetAttribute(gpt_flash, cudaFuncAttributeMaxDynamicSharedMemorySize, FLASH_SMEM);

    gpt_embed<<<(NT * DQ + 255) / 256, 256>>>(x, tok, pos, h);

    dim3 gP (DQ / 128,  NT / 128);        // (6,16)
    dim3 gQ (DQ / 128,  NT / 128, 3);     // (6,16,3)
    dim3 gF1(FFQ / 128, NT / 128);        // (24,16)
    dim3 gV ((VQ + 127) / 128, NT / 128); // (393,16)
    dim3 gFl(SQ / 64,   BQ * HQ);         // (8,48)

    for (int l = 0; l < LQ; l++) {
        const float* Wq = wq + (long)l * DQ * DQ;
        const float* Wk = wk + (long)l * DQ * DQ;
        const float* Wv = wv + (long)l * DQ * DQ;
        const float* Wo = wo + (long)l * DQ * DQ;
        const float* W1 = w1 + (long)l * DQ * FFQ;
        const float* W2 = w2 + (long)l * FFQ * DQ;

        gpt_ln<<<NT, 256>>>(h, ln1s + l * DQ, ln1b + l * DQ, hn);

        gpt_hmma_qkv<<<gQ, 256>>>(hn, Wq, Wk, Wv, q, k, v);

        gpt_flash<<<gFl, 256, FLASH_SMEM>>>(q, k, v, ctx);

        // h = h + ctx @ Wo + bo
        gpt_hmma<2, false><<<gP, 256>>>(ctx, Wo, bo + l * DQ, h, h,
            DQ, DQ, DQ, DQ, DQ);

        gpt_ln<<<NT, 256>>>(h, ln2s + l * DQ, ln2b + l * DQ, hn);

        // ff = gelu(hn @ W1 + b1)
        gpt_hmma<3, false><<<gF1, 256>>>(hn, W1, b1 + l * FFQ, nullptr, ff,
            FFQ, DQ, DQ, FFQ, FFQ);

        // h = h + ff @ W2 + b2
        gpt_hmma<2, false><<<gP, 256>>>(ff, W2, b2 + l * DQ, h, h,
            DQ, FFQ, FFQ, DQ, DQ);
    }

    gpt_ln<<<NT, 256>>>(h, fs, fb, hn);

    // logits = hn @ w_out : guarded N=50257
    gpt_hmma<0, true><<<gV, 256>>>(hn, wout, nullptr, nullptr, out,
        VQ, DQ, DQ, VQ, VQ);
}

// round 8
// speedup vs baseline: 3.5016x; 1.2829x over previous
#include <cuda_runtime.h>
#include <cuda_bf16.h>
#include <math.h>
#include <stdint.h>

// ---------------- problem constants ----------------
#define BQ   4
#define SQ   512
#define DQ   768
#define HQ   12
#define HDQ  64
#define LQ   12
#define VQ   50257
#define VQP  50304          // vocab padded to 128
#define FFQ  3072
#define NT   (BQ*SQ)        // 2048 tokens

// per-layer transposed-weight block offsets (elements)
#define WQ_OFF  0
#define WK_OFF  589824
#define WV_OFF  1179648
#define WO_OFF  1769472
#define W1T_OFF 2359296
#define W2T_OFF 4718592
#define LSZ     7077888
#define WOUT_OFF (12*LSZ)                 // 84934656
#define WTOT     (WOUT_OFF + (long)VQP*DQ) // 123568128 elements

// ---------------- static scratch (no allocs allowed) ----------------
__device__ __align__(128) float    g_h   [NT*DQ];
__device__ __align__(128) float    g_q   [NT*DQ];
__device__ __align__(128) float    g_k   [NT*DQ];
__device__ __align__(128) float    g_v   [NT*DQ];
__device__ __align__(128) uint16_t g_hnh [NT*DQ],  g_hnl [NT*DQ];
__device__ __align__(128) uint16_t g_ctxh[NT*DQ],  g_ctxl[NT*DQ];
__device__ __align__(128) uint16_t g_ffh [NT*FFQ], g_ffl [NT*FFQ];
__device__ __align__(128) uint16_t g_wth [WTOT];
__device__ __align__(128) uint16_t g_wtl [WTOT];

// ---------------- helpers ----------------
__device__ __forceinline__ float gelu_f(float x) {
    const float c = 0.7978845608028654f;
    float x3 = x * x * x;
    return 0.5f * x * (1.0f + tanhf(c * (x + 0.044715f * x3)));
}

__device__ __forceinline__ uint32_t smem_u32(const void* p) {
    uint32_t a;
    asm("{ .reg .u64 t; cvta.to.shared.u64 t, %1; cvt.u32.u64 %0, t; }" : "=r"(a) : "l"(p));
    return a;
}

__device__ __forceinline__ void split2(float a, float b, uint32_t& hi, uint32_t& lo) {
    __nv_bfloat16 ha = __float2bfloat16_rn(a), hb = __float2bfloat16_rn(b);
    float ra = a - __bfloat162float(ha), rb = b - __bfloat162float(hb);
    __nv_bfloat16 la = __float2bfloat16_rn(ra), lb = __float2bfloat16_rn(rb);
    hi = ((uint32_t)__bfloat16_as_ushort(hb) << 16) | (uint32_t)__bfloat16_as_ushort(ha);
    lo = ((uint32_t)__bfloat16_as_ushort(lb) << 16) | (uint32_t)__bfloat16_as_ushort(la);
}

__device__ __forceinline__ void ldsm4(uint32_t& r0, uint32_t& r1, uint32_t& r2, uint32_t& r3,
                                      uint32_t addr) {
    asm volatile("ldmatrix.sync.aligned.m8n8.x4.shared.b16 {%0,%1,%2,%3}, [%4];"
        : "=r"(r0), "=r"(r1), "=r"(r2), "=r"(r3) : "r"(addr));
}

__device__ __forceinline__ void mma_bf16(float* c, const uint32_t* a, const uint32_t* b) {
    asm volatile("mma.sync.aligned.m16n8k16.row.col.f32.bf16.bf16.f32 "
        "{%0,%1,%2,%3}, {%4,%5,%6,%7}, {%8,%9}, {%0,%1,%2,%3};"
        : "+f"(c[0]), "+f"(c[1]), "+f"(c[2]), "+f"(c[3])
        : "r"(a[0]), "r"(a[1]), "r"(a[2]), "r"(a[3]), "r"(b[0]), "r"(b[1]));
}

__device__ __forceinline__ void cpa16(uint32_t saddr, const void* g) {
    asm volatile("cp.async.cg.shared.global [%0], [%1], 16;" :: "r"(saddr), "l"(g));
}

// ---------------- weight transpose + split: W[K][N] fp32 -> Th/Tl[N][K] bf16 ----------------
__global__ void gpt_wsplit(const float* __restrict__ W, uint16_t* __restrict__ Th,
                           uint16_t* __restrict__ Tl, int K, int N, int Npad) {
    __shared__ float t[32][33];
    int n0 = blockIdx.x * 32, k0 = blockIdx.y * 32;
    int tx = threadIdx.x, ty = threadIdx.y;   // (32,8)
    #pragma unroll
    for (int j = 0; j < 4; j++) {
        int n = n0 + tx;
        t[ty + j * 8][tx] = (n < N) ? W[(long)(k0 + ty + j * 8) * N + n] : 0.f;
    }
    __syncthreads();
    #pragma unroll
    for (int j = 0; j < 4; j++) {
        int n = n0 + ty + j * 8;
        if (n < Npad) {
            float v = t[tx][ty + j * 8];
            __nv_bfloat16 hb = __float2bfloat16_rn(v);
            float r = v - __bfloat162float(hb);
            Th[(long)n * K + k0 + tx] = __bfloat16_as_ushort(hb);
            Tl[(long)n * K + k0 + tx] = __bfloat16_as_ushort(__float2bfloat16_rn(r));
        }
    }
}

// ---------------- embedding ----------------
__global__ void gpt_embed(const int* __restrict__ x, const float* __restrict__ tok,
                          const float* __restrict__ pos, float* __restrict__ h) {
    int i = blockIdx.x * blockDim.x + threadIdx.x;
    if (i < NT * DQ) {
        int t = i / DQ, d = i - t * DQ;
        int s = t & (SQ - 1);
        h[i] = tok[(long)x[t] * DQ + d] + pos[s * DQ + d];
    }
}

// ---------------- layernorm -> bf16 hi/lo ----------------
__global__ void gpt_ln(const float* __restrict__ in, const float* __restrict__ scale,
                       const float* __restrict__ shift,
                       uint16_t* __restrict__ oh, uint16_t* __restrict__ ol) {
    int t = blockIdx.x;
    const float* row = in + (long)t * DQ;
    __shared__ float red[256];
    int tid = threadIdx.x;

    float s = 0.f;
    for (int d = tid; d < DQ; d += 256) s += row[d];
    red[tid] = s; __syncthreads();
    for (int o = 128; o > 0; o >>= 1) { if (tid < o) red[tid] += red[tid + o]; __syncthreads(); }
    float mean = red[0] * (1.0f / DQ); __syncthreads();

    float sq = 0.f;
    for (int d = tid; d < DQ; d += 256) { float v = row[d] - mean; sq += v * v; }
    red[tid] = sq; __syncthreads();
    for (int o = 128; o > 0; o >>= 1) { if (tid < o) red[tid] += red[tid + o]; __syncthreads(); }
    float inv = rsqrtf(red[0] * (1.0f / DQ) + 1e-5f);

    long base = (long)t * DQ;
    for (int d = tid; d < DQ; d += 256) {
        float v = scale[d] * (row[d] - mean) * inv + shift[d];
        __nv_bfloat16 hb = __float2bfloat16_rn(v);
        float r = v - __bfloat162float(hb);
        oh[base + d] = __bfloat16_as_ushort(hb);
        ol[base + d] = __bfloat16_as_ushort(__float2bfloat16_rn(r));
    }
}

// ---------------- bf16x3 GEMM: pre-split operands + cp.async 2-stage pipeline ----------------
// A hi/lo: [M][K] bf16 (lda=K). B hi/lo: [Npad][K] bf16 (ldb=K), pad rows zeroed.
// CTA 128x128, 8 warps 2(m)x4(n), warp tile 64x32. K chunk 32.
// smem stage: Ah | Al | Bh | Bl, each 128 rows x 40 halves (80B rows). Stage = 40960B, x2.
#define STG 40960
#define OAL 10240
#define OBH 20480
#define OBL 30720

__device__ __forceinline__ void load_stage(uint32_t sst,
    const uint16_t* __restrict__ Ah, const uint16_t* __restrict__ Al,
    const uint16_t* __restrict__ Bh, const uint16_t* __restrict__ Bl,
    int bm, int bn, int K, int c, int tid) {
    #pragma unroll
    for (int p = 0; p < 2; p++) {
        int idx = tid + p * 256;
        int row = idx >> 2, seg = idx & 3;
        long go = (long)row * K + c * 32 + seg * 8;
        long ga = (long)bm * K + go;
        long gb = (long)bn * K + go;
        uint32_t so = row * 80 + seg * 16;
        cpa16(sst + so,       Ah + ga);
        cpa16(sst + OAL + so, Al + ga);
        cpa16(sst + OBH + so, Bh + gb);
        cpa16(sst + OBL + so, Bl + gb);
    }
    asm volatile("cp.async.commit_group;" ::: "memory");
}

__device__ __forceinline__ void mma_stage(uint32_t sst, float acc[4][4][4],
        int wm, int wn, int a_row, int a_kof, int b_nof, int b_kof) {
    #pragma unroll
    for (int kk = 0; kk < 32; kk += 16) {
        uint32_t fah[4][4], fal[4][4], fbh[4][2], fbl[4][2];
        #pragma unroll
        for (int ma = 0; ma < 4; ma++) {
            uint32_t ro = (uint32_t)((wm * 64 + ma * 16 + a_row) * 80 + (kk + a_kof) * 2);
            ldsm4(fah[ma][0], fah[ma][1], fah[ma][2], fah[ma][3], sst + ro);
            ldsm4(fal[ma][0], fal[ma][1], fal[ma][2], fal[ma][3], sst + OAL + ro);
        }
        #pragma unroll
        for (int np = 0; np < 2; np++) {
            uint32_t ro = (uint32_t)((wn * 32 + np * 16 + b_nof) * 80 + (kk + b_kof) * 2);
            ldsm4(fbh[2*np][0], fbh[2*np][1], fbh[2*np+1][0], fbh[2*np+1][1], sst + OBH + ro);
            ldsm4(fbl[2*np][0], fbl[2*np][1], fbl[2*np+1][0], fbl[2*np+1][1], sst + OBL + ro);
        }
        #pragma unroll
        for (int ma = 0; ma < 4; ma++)
            #pragma unroll
            for (int na = 0; na < 4; na++)
                mma_bf16(acc[ma][na], fah[ma], fbh[na]);
        #pragma unroll
        for (int ma = 0; ma < 4; ma++)
            #pragma unroll
            for (int na = 0; na < 4; na++)
                mma_bf16(acc[ma][na], fah[ma], fbl[na]);
        #pragma unroll
        for (int ma = 0; ma < 4; ma++)
            #pragma unroll
            for (int na = 0; na < 4; na++)
                mma_bf16(acc[ma][na], fal[ma], fbh[na]);
    }
}

// EPI: 0 fp32 plain; 2 fp32 +bias+res; 3 gelu(x+bias) -> bf16 hi/lo out. NG: guard gn (vocab).
template<int EPI, bool NG>
__device__ __forceinline__ void bmma_core(
    const uint16_t* __restrict__ Ah, const uint16_t* __restrict__ Al,
    const uint16_t* __restrict__ Bh, const uint16_t* __restrict__ Bl,
    const float* __restrict__ bias, const float* __restrict__ res,
    float* __restrict__ C, uint16_t* __restrict__ Ch, uint16_t* __restrict__ Cl,
    int Ntot, int K, int ldc) {
    extern __shared__ __align__(16) char smem[];
    uint32_t sb = smem_u32(smem);
    int tid = threadIdx.x;
    int lane = tid & 31, wid = tid >> 5;
    int wm = wid >> 2, wn = wid & 3;
    int bm = blockIdx.y * 128, bn = blockIdx.x * 128;

    int l8 = lane & 7;
    int a_row = ((lane >> 3) & 1) * 8 + l8;
    int a_kof = (lane >> 4) * 8;
    int b_nof = (lane >> 4) * 8 + l8;
    int b_kof = ((lane >> 3) & 1) * 8;

    float acc[4][4][4];
    #pragma unroll
    for (int i = 0; i < 4; i++)
        #pragma unroll
        for (int j = 0; j < 4; j++)
            #pragma unroll
            for (int r2 = 0; r2 < 4; r2++) acc[i][j][r2] = 0.f;

    const int NCH = K >> 5;
    load_stage(sb, Ah, Al, Bh, Bl, bm, bn, K, 0, tid);

    for (int c = 0; c < NCH; c++) {
        if (c + 1 < NCH) {
            load_stage(sb + ((c + 1) & 1) * STG, Ah, Al, Bh, Bl, bm, bn, K, c + 1, tid);
            asm volatile("cp.async.wait_group 1;" ::: "memory");
        } else {
            asm volatile("cp.async.wait_group 0;" ::: "memory");
        }
        __syncthreads();
        mma_stage(sb + (c & 1) * STG, acc, wm, wn, a_row, a_kof, b_nof, b_kof);
        if (c + 1 < NCH) __syncthreads();
    }

    // epilogue: registers -> gmem
    int g = lane >> 2, tig = lane & 3;
    #pragma unroll
    for (int ma = 0; ma < 4; ma++) {
        int r0 = bm + wm * 64 + ma * 16 + g;
        #pragma unroll
        for (int na = 0; na < 4; na++) {
            int gn = bn + wn * 32 + na * 8 + 2 * tig;
            #pragma unroll
            for (int half = 0; half < 2; half++) {
                int gm = r0 + half * 8;
                float v0 = acc[ma][na][half * 2 + 0];
                float v1 = acc[ma][na][half * 2 + 1];
                long gi = (long)gm * ldc + gn;
                if (NG) {
                    if (gn < Ntot)     C[gi]     = v0;
                    if (gn + 1 < Ntot) C[gi + 1] = v1;
                } else if (EPI == 3) {
                    v0 = gelu_f(v0 + bias[gn]);
                    v1 = gelu_f(v1 + bias[gn + 1]);
                    uint32_t hh, ll;
                    split2(v0, v1, hh, ll);
                    *(uint32_t*)&Ch[gi] = hh;
                    *(uint32_t*)&Cl[gi] = ll;
                } else {
                    if (EPI == 2) {
                        v0 += bias[gn]     + res[gi];
                        v1 += bias[gn + 1] + res[gi + 1];
                    }
                    *(float2*)&C[gi] = make_float2(v0, v1);
                }
            }
        }
    }
}

template<int EPI, bool NG>
__global__ void __launch_bounds__(256, 1)
gpt_bmma(const uint16_t* __restrict__ Ah, const uint16_t* __restrict__ Al,
         const uint16_t* __restrict__ Bh, const uint16_t* __restrict__ Bl,
         const float* __restrict__ bias, const float* __restrict__ res,
         float* __restrict__ C, uint16_t* __restrict__ Ch, uint16_t* __restrict__ Cl,
         int Ntot, int K, int ldc) {
    bmma_core<EPI, NG>(Ah, Al, Bh, Bl, bias, res, C, Ch, Cl, Ntot, K, ldc);
}

__global__ void __launch_bounds__(256, 1)
gpt_bmma_qkv(const uint16_t* __restrict__ Ah, const uint16_t* __restrict__ Al,
             const uint16_t* __restrict__ Wth, const uint16_t* __restrict__ Wtl,
             float* __restrict__ Oq, float* __restrict__ Ok, float* __restrict__ Ov) {
    int z = blockIdx.z;
    const uint16_t* Bh = Wth + (long)z * 589824;
    const uint16_t* Bl = Wtl + (long)z * 589824;
    float* C = (z == 0) ? Oq : (z == 1) ? Ok : Ov;
    bmma_core<0, false>(Ah, Al, Bh, Bl, nullptr, nullptr, C, nullptr, nullptr, DQ, DQ, DQ);
}

// ---------------- fused flash attention (epilogue -> bf16 hi/lo ctx) ----------------
__global__ void __launch_bounds__(256, 2)
gpt_flash(const float* __restrict__ Q, const float* __restrict__ Kx,
          const float* __restrict__ Vx,
          uint16_t* __restrict__ ctxh, uint16_t* __restrict__ ctxl) {
    extern __shared__ float sm[];
    float* Qs   = sm;
    float* Ks   = sm + 4096;
    float* Vs   = sm + 8192;
    float* rowm = sm + 12288;
    float* rowl = rowm + 64;
    float* rowf = rowm + 128;

    int z = blockIdx.y;
    int b = z / HQ, h = z - b * HQ;
    int qt = blockIdx.x, q0 = qt * 64;
    int tid = threadIdx.x;
    int r = tid & 63, dg = tid >> 6;
    int ty = tid >> 4, tx = tid & 15;

    {
        const float* qrow = Q + ((long)(b * SQ + q0 + r)) * DQ + h * HDQ + dg * 16;
        #pragma unroll
        for (int i = 0; i < 4; i++) {
            float4 t = *(const float4*)(qrow + i * 4);
            int d = dg * 16 + i * 4;
            Qs[(d + 0) * 64 + r] = t.x; Qs[(d + 1) * 64 + r] = t.y;
            Qs[(d + 2) * 64 + r] = t.z; Qs[(d + 3) * 64 + r] = t.w;
        }
    }
    if (tid < 64) { rowm[tid] = -1e30f; rowl[tid] = 0.f; }

    float o[4][4] = {};

    for (int j = 0; j <= qt; j++) {
        int k0 = j * 64;
        __syncthreads();
        {
            const float* krow = Kx + ((long)(b * SQ + k0 + r)) * DQ + h * HDQ + dg * 16;
            const float* vrow = Vx + ((long)(b * SQ + k0 + r)) * DQ + h * HDQ + dg * 16;
            #pragma unroll
            for (int i = 0; i < 4; i++) {
                float4 t = *(const float4*)(krow + i * 4);
                int d = dg * 16 + i * 4;
                Ks[(d + 0) * 64 + r] = t.x; Ks[(d + 1) * 64 + r] = t.y;
                Ks[(d + 2) * 64 + r] = t.z; Ks[(d + 3) * 64 + r] = t.w;
                float4 tv = *(const float4*)(vrow + i * 4);
                *(float4*)&Vs[r * 64 + dg * 16 + i * 4] = tv;
            }
        }
        __syncthreads();

        float s[4][4] = {};
        #pragma unroll 8
        for (int d = 0; d < 64; d++) {
            float qv[4], kv[4];
            #pragma unroll
            for (int i = 0; i < 4; i++) qv[i] = Qs[d * 64 + ty * 4 + i];
            #pragma unroll
            for (int c = 0; c < 4; c++) kv[c] = Ks[d * 64 + tx * 4 + c];
            #pragma unroll
            for (int i = 0; i < 4; i++)
                #pragma unroll
                for (int c = 0; c < 4; c++)
                    s[i][c] += qv[i] * kv[c];
        }
        #pragma unroll
        for (int i = 0; i < 4; i++)
            #pragma unroll
            for (int c = 0; c < 4; c++) {
                s[i][c] *= 0.125f;
                if (j == qt && (k0 + tx * 4 + c) > (q0 + ty * 4 + i)) s[i][c] = -1e30f;
            }
        __syncthreads();
        #pragma unroll
        for (int i = 0; i < 4; i++)
            #pragma unroll
            for (int c = 0; c < 4; c++)
                Ks[(ty * 4 + i) * 64 + tx * 4 + c] = s[i][c];
        __syncthreads();

        if (tid < 64) {
            float m_old = rowm[tid], m = m_old;
            #pragma unroll 8
            for (int t = 0; t < 64; t++) {
                int kk = (t + tid) & 63;
                m = fmaxf(m, Ks[tid * 64 + kk]);
            }
            float f = __expf(m_old - m);
            float l = rowl[tid] * f;
            #pragma unroll 8
            for (int t = 0; t < 64; t++) {
                int kk = (t + tid) & 63;
                float p = __expf(Ks[tid * 64 + kk] - m);
                Ks[tid * 64 + kk] = p;
                l += p;
            }
            rowm[tid] = m; rowl[tid] = l; rowf[tid] = f;
        }
        __syncthreads();

        float fr[4];
        #pragma unroll
        for (int i = 0; i < 4; i++) fr[i] = rowf[ty * 4 + i];
        #pragma unroll
        for (int i = 0; i < 4; i++)
            #pragma unroll
            for (int c = 0; c < 4; c++) o[i][c] *= fr[i];
        #pragma unroll 8
        for (int kk = 0; kk < 64; kk++) {
            float p[4];
            #pragma unroll
            for (int i = 0; i < 4; i++) p[i] = Ks[(ty * 4 + i) * 64 + kk];
            float4 vv = *(const float4*)&Vs[kk * 64 + tx * 4];
            #pragma unroll
            for (int i = 0; i < 4; i++) {
                o[i][0] += p[i] * vv.x; o[i][1] += p[i] * vv.y;
                o[i][2] += p[i] * vv.z; o[i][3] += p[i] * vv.w;
            }
        }
    }

    #pragma unroll
    for (int i = 0; i < 4; i++) {
        float inv = 1.0f / rowl[ty * 4 + i];
        float v0 = o[i][0] * inv, v1 = o[i][1] * inv;
        float v2 = o[i][2] * inv, v3 = o[i][3] * inv;
        uint32_t h01, l01, h23, l23;
        split2(v0, v1, h01, l01);
        split2(v2, v3, h23, l23);
        long base = ((long)(b * SQ + q0 + ty * 4 + i)) * DQ + h * HDQ + tx * 4;
        *(uint2*)&ctxh[base] = make_uint2(h01, h23);
        *(uint2*)&ctxl[base] = make_uint2(l01, l23);
    }
}

// ---------------- host orchestration ----------------
extern "C" void kernel_launch(void* const* d_in, const int* in_sizes, int n_in,
                              void* d_out, int out_size) {
    const int*   x    = (const int*)  d_in[0];
    const float* tok  = (const float*)d_in[1];
    const float* pos  = (const float*)d_in[2];
    const float* ln1s = (const float*)d_in[3];
    const float* ln1b = (const float*)d_in[4];
    const float* wq   = (const float*)d_in[5];
    const float* wk   = (const float*)d_in[6];
    const float* wv   = (const float*)d_in[7];
    const float* wo   = (const float*)d_in[8];
    const float* bo   = (const float*)d_in[9];
    const float* ln2s = (const float*)d_in[10];
    const float* ln2b = (const float*)d_in[11];
    const float* w1   = (const float*)d_in[12];
    const float* b1   = (const float*)d_in[13];
    const float* w2   = (const float*)d_in[14];
    const float* b2   = (const float*)d_in[15];
    const float* fs   = (const float*)d_in[16];
    const float* fb   = (const float*)d_in[17];
    const float* wout = (const float*)d_in[18];
    float* out = (float*)d_out;

    float *h, *q, *k, *v;
    uint16_t *hnh, *hnl, *ctxh, *ctxl, *ffh, *ffl, *wth, *wtl;
    cudaGetSymbolAddress((void**)&h,    g_h);
    cudaGetSymbolAddress((void**)&q,    g_q);
    cudaGetSymbolAddress((void**)&k,    g_k);
    cudaGetSymbolAddress((void**)&v,    g_v);
    cudaGetSymbolAddress((void**)&hnh,  g_hnh);
    cudaGetSymbolAddress((void**)&hnl,  g_hnl);
    cudaGetSymbolAddress((void**)&ctxh, g_ctxh);
    cudaGetSymbolAddress((void**)&ctxl, g_ctxl);
    cudaGetSymbolAddress((void**)&ffh,  g_ffh);
    cudaGetSymbolAddress((void**)&ffl,  g_ffl);
    cudaGetSymbolAddress((void**)&wth,  g_wth);
    cudaGetSymbolAddress((void**)&wtl,  g_wtl);

    const int FLASH_SMEM = (64 * 64 * 3 + 64 * 3) * sizeof(float); // 49920
    const int BMMA_SMEM  = 2 * STG;                                 // 81920
    cudaFuncSetAttribute(gpt_flash, cudaFuncAttributeMaxDynamicSharedMemorySize, FLASH_SMEM);
    cudaFuncSetAttribute((const void*)gpt_bmma<2, false>, cudaFuncAttributeMaxDynamicSharedMemorySize, BMMA_SMEM);
    cudaFuncSetAttribute((const void*)gpt_bmma<3, false>, cudaFuncAttributeMaxDynamicSharedMemorySize, BMMA_SMEM);
    cudaFuncSetAttribute((const void*)gpt_bmma<0, true>,  cudaFuncAttributeMaxDynamicSharedMemorySize, BMMA_SMEM);
    cudaFuncSetAttribute((const void*)gpt_bmma_qkv,       cudaFuncAttributeMaxDynamicSharedMemorySize, BMMA_SMEM);

    // ---- one-time (per call) weight transpose+split ----
    dim3 wt(32, 8);
    for (int l = 0; l < LQ; l++) {
        long lo = (long)l * LSZ;
        gpt_wsplit<<<dim3(24, 24), wt>>>(wq + (long)l*DQ*DQ,  wth + lo + WQ_OFF,  wtl + lo + WQ_OFF,  DQ, DQ, DQ);
        gpt_wsplit<<<dim3(24, 24), wt>>>(wk + (long)l*DQ*DQ,  wth + lo + WK_OFF,  wtl + lo + WK_OFF,  DQ, DQ, DQ);
        gpt_wsplit<<<dim3(24, 24), wt>>>(wv + (long)l*DQ*DQ,  wth + lo + WV_OFF,  wtl + lo + WV_OFF,  DQ, DQ, DQ);
        gpt_wsplit<<<dim3(24, 24), wt>>>(wo + (long)l*DQ*DQ,  wth + lo + WO_OFF,  wtl + lo + WO_OFF,  DQ, DQ, DQ);
        gpt_wsplit<<<dim3(96, 24), wt>>>(w1 + (long)l*DQ*FFQ, wth + lo + W1T_OFF, wtl + lo + W1T_OFF, DQ, FFQ, FFQ);
        gpt_wsplit<<<dim3(24, 96), wt>>>(w2 + (long)l*FFQ*DQ, wth + lo + W2T_OFF, wtl + lo + W2T_OFF, FFQ, DQ, DQ);
    }
    gpt_wsplit<<<dim3(VQP / 32, 24), wt>>>(wout, wth + WOUT_OFF, wtl + WOUT_OFF, DQ, VQ, VQP);

    gpt_embed<<<(NT * DQ + 255) / 256, 256>>>(x, tok, pos, h);

    dim3 gP (DQ / 128,  NT / 128);        // (6,16)
    dim3 gQ (DQ / 128,  NT / 128, 3);     // (6,16,3)
    dim3 gF1(FFQ / 128, NT / 128);        // (24,16)
    dim3 gV (VQP / 128, NT / 128);        // (393,16)
    dim3 gFl(SQ / 64,   BQ * HQ);         // (8,48)

    for (int l = 0; l < LQ; l++) {
        long lo = (long)l * LSZ;

        gpt_ln<<<NT, 256>>>(h, ln1s + l * DQ, ln1b + l * DQ, hnh, hnl);

        gpt_bmma_qkv<<<gQ, 256, BMMA_SMEM>>>(hnh, hnl, wth + lo + WQ_OFF, wtl + lo + WQ_OFF, q, k, v);

        gpt_flash<<<gFl, 256, FLASH_SMEM>>>(q, k, v, ctxh, ctxl);

        // h = h + ctx @ Wo + bo
        gpt_bmma<2, false><<<gP, 256, BMMA_SMEM>>>(ctxh, ctxl,
            wth + lo + WO_OFF, wtl + lo + WO_OFF, bo + l * DQ, h, h, nullptr, nullptr,
            DQ, DQ, DQ);

        gpt_ln<<<NT, 256>>>(h, ln2s + l * DQ, ln2b + l * DQ, hnh, hnl);

        // ff = gelu(hn @ W1 + b1) -> bf16 hi/lo
        gpt_bmma<3, false><<<gF1, 256, BMMA_SMEM>>>(hnh, hnl,
            wth + lo + W1T_OFF, wtl + lo + W1T_OFF, b1 + l * FFQ, nullptr,
            nullptr, ffh, ffl, FFQ, DQ, FFQ);

        // h = h + ff @ W2 + b2
        gpt_bmma<2, false><<<gP, 256, BMMA_SMEM>>>(ffh, ffl,
            wth + lo + W2T_OFF, wtl + lo + W2T_OFF, b2 + l * DQ, h, h, nullptr, nullptr,
            DQ, FFQ, DQ);
    }

    gpt_ln<<<NT, 256>>>(h, fs, fb, hnh, hnl);

    // logits = hn @ w_out (guarded N)
    gpt_bmma<0, true><<<gV, 256, BMMA_SMEM>>>(hnh, hnl,
        wth + WOUT_OFF, wtl + WOUT_OFF, nullptr, nullptr, out, nullptr, nullptr,
        VQ, DQ, VQ);
}

// round 9
// speedup vs baseline: 3.5386x; 1.0106x over previous
#include <cuda_runtime.h>
#include <cuda_bf16.h>
#include <math.h>
#include <stdint.h>

// ---------------- problem constants ----------------
#define BQ   4
#define SQ   512
#define DQ   768
#define HQ   12
#define HDQ  64
#define LQ   12
#define VQ   50257
#define VQP  50304
#define FFQ  3072
#define NT   (BQ*SQ)

#define WQ_OFF  0
#define WK_OFF  589824
#define WV_OFF  1179648
#define WO_OFF  1769472
#define W1T_OFF 2359296
#define W2T_OFF 4718592
#define LSZ     7077888
#define WOUT_OFF (12*LSZ)
#define WTOT     (WOUT_OFF + (long)VQP*DQ)

// ---------------- static scratch ----------------
__device__ __align__(128) float    g_h   [NT*DQ];
__device__ __align__(128) float    g_q   [NT*DQ];
__device__ __align__(128) float    g_k   [NT*DQ];
__device__ __align__(128) float    g_v   [NT*DQ];
__device__ __align__(128) uint16_t g_hnh [NT*DQ],  g_hnl [NT*DQ];
__device__ __align__(128) uint16_t g_ctxh[NT*DQ],  g_ctxl[NT*DQ];
__device__ __align__(128) uint16_t g_ffh [NT*FFQ], g_ffl [NT*FFQ];
__device__ __align__(128) uint16_t g_wth [WTOT];
__device__ __align__(128) uint16_t g_wtl [WTOT];

// ---------------- helpers ----------------
__device__ __forceinline__ float gelu_f(float x) {
    const float c = 0.7978845608028654f;
    float x3 = x * x * x;
    return 0.5f * x * (1.0f + tanhf(c * (x + 0.044715f * x3)));
}

__device__ __forceinline__ uint32_t smem_u32(const void* p) {
    uint32_t a;
    asm("{ .reg .u64 t; cvta.to.shared.u64 t, %1; cvt.u32.u64 %0, t; }" : "=r"(a) : "l"(p));
    return a;
}

__device__ __forceinline__ void split2(float a, float b, uint32_t& hi, uint32_t& lo) {
    __nv_bfloat16 ha = __float2bfloat16_rn(a), hb = __float2bfloat16_rn(b);
    float ra = a - __bfloat162float(ha), rb = b - __bfloat162float(hb);
    __nv_bfloat16 la = __float2bfloat16_rn(ra), lb = __float2bfloat16_rn(rb);
    hi = ((uint32_t)__bfloat16_as_ushort(hb) << 16) | (uint32_t)__bfloat16_as_ushort(ha);
    lo = ((uint32_t)__bfloat16_as_ushort(lb) << 16) | (uint32_t)__bfloat16_as_ushort(la);
}

__device__ __forceinline__ void ldsm4(uint32_t& r0, uint32_t& r1, uint32_t& r2, uint32_t& r3,
                                      uint32_t addr) {
    asm volatile("ldmatrix.sync.aligned.m8n8.x4.shared.b16 {%0,%1,%2,%3}, [%4];"
        : "=r"(r0), "=r"(r1), "=r"(r2), "=r"(r3) : "r"(addr));
}

__device__ __forceinline__ void mma_bf16(float* c, const uint32_t* a, const uint32_t* b) {
    asm volatile("mma.sync.aligned.m16n8k16.row.col.f32.bf16.bf16.f32 "
        "{%0,%1,%2,%3}, {%4,%5,%6,%7}, {%8,%9}, {%0,%1,%2,%3};"
        : "+f"(c[0]), "+f"(c[1]), "+f"(c[2]), "+f"(c[3])
        : "r"(a[0]), "r"(a[1]), "r"(a[2]), "r"(a[3]), "r"(b[0]), "r"(b[1]));
}

__device__ __forceinline__ void cpa16(uint32_t saddr, const void* g) {
    asm volatile("cp.async.cg.shared.global [%0], [%1], 16;" :: "r"(saddr), "l"(g));
}

// ---------------- weight transpose+split, batched over layers (grid.z) ----------------
__global__ void gpt_wsplit(const float* __restrict__ W, uint16_t* __restrict__ Th,
                           uint16_t* __restrict__ Tl, int K, int N, int Npad,
                           long ws, long ts) {
    int l = blockIdx.z;
    W  += (long)l * ws;
    Th += (long)l * ts;
    Tl += (long)l * ts;
    __shared__ float t[32][33];
    int n0 = blockIdx.x * 32, k0 = blockIdx.y * 32;
    int tx = threadIdx.x, ty = threadIdx.y;
    #pragma unroll
    for (int j = 0; j < 4; j++) {
        int n = n0 + tx;
        t[ty + j * 8][tx] = (n < N) ? W[(long)(k0 + ty + j * 8) * N + n] : 0.f;
    }
    __syncthreads();
    #pragma unroll
    for (int j = 0; j < 4; j++) {
        int n = n0 + ty + j * 8;
        if (n < Npad) {
            float v = t[tx][ty + j * 8];
            __nv_bfloat16 hb = __float2bfloat16_rn(v);
            float r = v - __bfloat162float(hb);
            Th[(long)n * K + k0 + tx] = __bfloat16_as_ushort(hb);
            Tl[(long)n * K + k0 + tx] = __bfloat16_as_ushort(__float2bfloat16_rn(r));
        }
    }
}

// ---------------- embedding ----------------
__global__ void gpt_embed(const int* __restrict__ x, const float* __restrict__ tok,
                          const float* __restrict__ pos, float* __restrict__ h) {
    int i = blockIdx.x * blockDim.x + threadIdx.x;
    if (i < NT * DQ) {
        int t = i / DQ, d = i - t * DQ;
        int s = t & (SQ - 1);
        h[i] = tok[(long)x[t] * DQ + d] + pos[s * DQ + d];
    }
}

// ---------------- layernorm -> bf16 hi/lo ----------------
__global__ void gpt_ln(const float* __restrict__ in, const float* __restrict__ scale,
                       const float* __restrict__ shift,
                       uint16_t* __restrict__ oh, uint16_t* __restrict__ ol) {
    int t = blockIdx.x;
    const float* row = in + (long)t * DQ;
    __shared__ float red[256];
    int tid = threadIdx.x;

    float s = 0.f;
    for (int d = tid; d < DQ; d += 256) s += row[d];
    red[tid] = s; __syncthreads();
    for (int o = 128; o > 0; o >>= 1) { if (tid < o) red[tid] += red[tid + o]; __syncthreads(); }
    float mean = red[0] * (1.0f / DQ); __syncthreads();

    float sq = 0.f;
    for (int d = tid; d < DQ; d += 256) { float v = row[d] - mean; sq += v * v; }
    red[tid] = sq; __syncthreads();
    for (int o = 128; o > 0; o >>= 1) { if (tid < o) red[tid] += red[tid + o]; __syncthreads(); }
    float inv = rsqrtf(red[0] * (1.0f / DQ) + 1e-5f);

    long base = (long)t * DQ;
    for (int d = tid; d < DQ; d += 256) {
        float v = scale[d] * (row[d] - mean) * inv + shift[d];
        __nv_bfloat16 hb = __float2bfloat16_rn(v);
        float r = v - __bfloat162float(hb);
        oh[base + d] = __bfloat16_as_ushort(hb);
        ol[base + d] = __bfloat16_as_ushort(__float2bfloat16_rn(r));
    }
}

// ---------------- bf16x3 GEMM, 2-stage cp.async pipeline, BM templated ----------------
// stage: Ah(BM rows) | Al | Bh(128) | Bl, rows of 80B (32 K-halves + pad).
template<int BM>
__device__ __forceinline__ void load_stage(uint32_t sst,
    const uint16_t* __restrict__ Ah, const uint16_t* __restrict__ Al,
    const uint16_t* __restrict__ Bh, const uint16_t* __restrict__ Bl,
    int bm, int bn, int K, int c, int tid) {
    constexpr int OAL = BM * 80, OBH = 2 * BM * 80, OBL = OBH + 10240;
    #pragma unroll
    for (int p = 0; p < 2; p++) {
        int idx = tid + p * 256;
        int row = idx >> 2, seg = idx & 3;
        long go = (long)row * K + c * 32 + seg * 8;
        uint32_t so = row * 80 + seg * 16;
        cpa16(sst + OBH + so, Bh + (long)bn * K + go);
        cpa16(sst + OBL + so, Bl + (long)bn * K + go);
        if (BM == 128 || row < BM) {
            cpa16(sst + so,       Ah + (long)bm * K + go);
            cpa16(sst + OAL + so, Al + (long)bm * K + go);
        }
    }
    asm volatile("cp.async.commit_group;" ::: "memory");
}

template<int BM>
__device__ __forceinline__ void mma_stage(uint32_t sst, float acc[][4][4],
        int wm, int wn, int a_row, int a_kof, int b_nof, int b_kof) {
    constexpr int MA = BM / 32;
    constexpr int OAL = BM * 80, OBH = 2 * BM * 80, OBL = OBH + 10240;
    #pragma unroll
    for (int kk = 0; kk < 32; kk += 16) {
        uint32_t fah[MA][4], fal[MA][4], fbh[4][2], fbl[4][2];
        #pragma unroll
        for (int ma = 0; ma < MA; ma++) {
            uint32_t ro = (uint32_t)((wm * (BM / 2) + ma * 16 + a_row) * 80 + (kk + a_kof) * 2);
            ldsm4(fah[ma][0], fah[ma][1], fah[ma][2], fah[ma][3], sst + ro);
        }
        #pragma unroll
        for (int np = 0; np < 2; np++) {
            uint32_t ro = (uint32_t)((wn * 32 + np * 16 + b_nof) * 80 + (kk + b_kof) * 2);
            ldsm4(fbh[2*np][0], fbh[2*np][1], fbh[2*np+1][0], fbh[2*np+1][1], sst + OBH + ro);
        }
        #pragma unroll
        for (int ma = 0; ma < MA; ma++)
            #pragma unroll
            for (int na = 0; na < 4; na++)
                mma_bf16(acc[ma][na], fah[ma], fbh[na]);
        #pragma unroll
        for (int np = 0; np < 2; np++) {
            uint32_t ro = (uint32_t)((wn * 32 + np * 16 + b_nof) * 80 + (kk + b_kof) * 2);
            ldsm4(fbl[2*np][0], fbl[2*np][1], fbl[2*np+1][0], fbl[2*np+1][1], sst + OBL + ro);
        }
        #pragma unroll
        for (int ma = 0; ma < MA; ma++)
            #pragma unroll
            for (int na = 0; na < 4; na++)
                mma_bf16(acc[ma][na], fah[ma], fbl[na]);
        #pragma unroll
        for (int ma = 0; ma < MA; ma++) {
            uint32_t ro = (uint32_t)((wm * (BM / 2) + ma * 16 + a_row) * 80 + (kk + a_kof) * 2);
            ldsm4(fal[ma][0], fal[ma][1], fal[ma][2], fal[ma][3], sst + OAL + ro);
        }
        #pragma unroll
        for (int ma = 0; ma < MA; ma++)
            #pragma unroll
            for (int na = 0; na < 4; na++)
                mma_bf16(acc[ma][na], fal[ma], fbh[na]);
    }
}

// EPI: 0 fp32 plain; 2 fp32 +bias+res; 3 gelu(x+bias)->bf16 hi/lo. NG: guard gn.
template<int EPI, bool NG, int BM>
__device__ __forceinline__ void bmma_core(
    const uint16_t* __restrict__ Ah, const uint16_t* __restrict__ Al,
    const uint16_t* __restrict__ Bh, const uint16_t* __restrict__ Bl,
    const float* __restrict__ bias, const float* __restrict__ res,
    float* __restrict__ C, uint16_t* __restrict__ Ch, uint16_t* __restrict__ Cl,
    int Ntot, int K, int ldc, int miter) {
    constexpr int MA = BM / 32;
    constexpr int STG = (2 * BM + 256) * 80;
    extern __shared__ __align__(16) char smem[];
    uint32_t sb = smem_u32(smem);
    int tid = threadIdx.x;
    int lane = tid & 31, wid = tid >> 5;
    int wm = wid >> 2, wn = wid & 3;
    int bn = blockIdx.x * 128;

    int l8 = lane & 7;
    int a_row = ((lane >> 3) & 1) * 8 + l8;
    int a_kof = (lane >> 4) * 8;
    int b_nof = (lane >> 4) * 8 + l8;
    int b_kof = ((lane >> 3) & 1) * 8;
    int g = lane >> 2, tig = lane & 3;
    const int NCH = K >> 5;

    for (int mi = 0; mi < miter; mi++) {
        int bm = (blockIdx.y * miter + mi) * BM;
        if (mi) __syncthreads();

        float acc[MA][4][4];
        #pragma unroll
        for (int i = 0; i < MA; i++)
            #pragma unroll
            for (int j = 0; j < 4; j++)
                #pragma unroll
                for (int r2 = 0; r2 < 4; r2++) acc[i][j][r2] = 0.f;

        load_stage<BM>(sb, Ah, Al, Bh, Bl, bm, bn, K, 0, tid);

        for (int c = 0; c < NCH; c++) {
            if (c + 1 < NCH) {
                load_stage<BM>(sb + ((c + 1) & 1) * STG, Ah, Al, Bh, Bl, bm, bn, K, c + 1, tid);
                asm volatile("cp.async.wait_group 1;" ::: "memory");
            } else {
                asm volatile("cp.async.wait_group 0;" ::: "memory");
            }
            __syncthreads();
            mma_stage<BM>(sb + (c & 1) * STG, acc, wm, wn, a_row, a_kof, b_nof, b_kof);
            if (c + 1 < NCH) __syncthreads();
        }

        #pragma unroll
        for (int ma = 0; ma < MA; ma++) {
            int r0 = bm + wm * (BM / 2) + ma * 16 + g;
            #pragma unroll
            for (int na = 0; na < 4; na++) {
                int gn = bn + wn * 32 + na * 8 + 2 * tig;
                #pragma unroll
                for (int half = 0; half < 2; half++) {
                    int gm = r0 + half * 8;
                    float v0 = acc[ma][na][half * 2 + 0];
                    float v1 = acc[ma][na][half * 2 + 1];
                    long gi = (long)gm * ldc + gn;
                    if (NG) {
                        if (gn < Ntot)     C[gi]     = v0;
                        if (gn + 1 < Ntot) C[gi + 1] = v1;
                    } else if (EPI == 3) {
                        v0 = gelu_f(v0 + bias[gn]);
                        v1 = gelu_f(v1 + bias[gn + 1]);
                        uint32_t hh, ll;
                        split2(v0, v1, hh, ll);
                        *(uint32_t*)&Ch[gi] = hh;
                        *(uint32_t*)&Cl[gi] = ll;
                    } else {
                        if (EPI == 2) {
                            v0 += bias[gn]     + res[gi];
                            v1 += bias[gn + 1] + res[gi + 1];
                        }
                        *(float2*)&C[gi] = make_float2(v0, v1);
                    }
                }
            }
        }
    }
}

template<int EPI, bool NG, int BM>
__global__ void __launch_bounds__(256, 2)
gpt_bmma(const uint16_t* __restrict__ Ah, const uint16_t* __restrict__ Al,
         const uint16_t* __restrict__ Bh, const uint16_t* __restrict__ Bl,
         const float* __restrict__ bias, const float* __restrict__ res,
         float* __restrict__ C, uint16_t* __restrict__ Ch, uint16_t* __restrict__ Cl,
         int Ntot, int K, int ldc, int miter) {
    bmma_core<EPI, NG, BM>(Ah, Al, Bh, Bl, bias, res, C, Ch, Cl, Ntot, K, ldc, miter);
}

__global__ void __launch_bounds__(256, 2)
gpt_bmma_qkv(const uint16_t* __restrict__ Ah, const uint16_t* __restrict__ Al,
             const uint16_t* __restrict__ Wth, const uint16_t* __restrict__ Wtl,
             float* __restrict__ Oq, float* __restrict__ Ok, float* __restrict__ Ov) {
    int z = blockIdx.z;
    const uint16_t* Bh = Wth + (long)z * 589824;
    const uint16_t* Bl = Wtl + (long)z * 589824;
    float* C = (z == 0) ? Oq : (z == 1) ? Ok : Ov;
    bmma_core<0, false, 128>(Ah, Al, Bh, Bl, nullptr, nullptr, C, nullptr, nullptr,
                             DQ, DQ, DQ, 1);
}

// ---------------- fused flash attention (epilogue -> bf16 hi/lo ctx) ----------------
__global__ void __launch_bounds__(256, 2)
gpt_flash(const float* __restrict__ Q, const float* __restrict__ Kx,
          const float* __restrict__ Vx,
          uint16_t* __restrict__ ctxh, uint16_t* __restrict__ ctxl) {
    extern __shared__ float sm[];
    float* Qs   = sm;
    float* Ks   = sm + 4096;
    float* Vs   = sm + 8192;
    float* rowm = sm + 12288;
    float* rowl = rowm + 64;
    float* rowf = rowm + 128;

    int z = blockIdx.y;
    int b = z / HQ, h = z - b * HQ;
    int qt = blockIdx.x, q0 = qt * 64;
    int tid = threadIdx.x;
    int r = tid & 63, dg = tid >> 6;
    int ty = tid >> 4, tx = tid & 15;

    {
        const float* qrow = Q + ((long)(b * SQ + q0 + r)) * DQ + h * HDQ + dg * 16;
        #pragma unroll
        for (int i = 0; i < 4; i++) {
            float4 t = *(const float4*)(qrow + i * 4);
            int d = dg * 16 + i * 4;
            Qs[(d + 0) * 64 + r] = t.x; Qs[(d + 1) * 64 + r] = t.y;
            Qs[(d + 2) * 64 + r] = t.z; Qs[(d + 3) * 64 + r] = t.w;
        }
    }
    if (tid < 64) { rowm[tid] = -1e30f; rowl[tid] = 0.f; }

    float o[4][4] = {};

    for (int j = 0; j <= qt; j++) {
        int k0 = j * 64;
        __syncthreads();
        {
            const float* krow = Kx + ((long)(b * SQ + k0 + r)) * DQ + h * HDQ + dg * 16;
            const float* vrow = Vx + ((long)(b * SQ + k0 + r)) * DQ + h * HDQ + dg * 16;
            #pragma unroll
            for (int i = 0; i < 4; i++) {
                float4 t = *(const float4*)(krow + i * 4);
                int d = dg * 16 + i * 4;
                Ks[(d + 0) * 64 + r] = t.x; Ks[(d + 1) * 64 + r] = t.y;
                Ks[(d + 2) * 64 + r] = t.z; Ks[(d + 3) * 64 + r] = t.w;
                float4 tv = *(const float4*)(vrow + i * 4);
                *(float4*)&Vs[r * 64 + dg * 16 + i * 4] = tv;
            }
        }
        __syncthreads();

        float s[4][4] = {};
        #pragma unroll 8
        for (int d = 0; d < 64; d++) {
            float qv[4], kv[4];
            #pragma unroll
            for (int i = 0; i < 4; i++) qv[i] = Qs[d * 64 + ty * 4 + i];
            #pragma unroll
            for (int c = 0; c < 4; c++) kv[c] = Ks[d * 64 + tx * 4 + c];
            #pragma unroll
            for (int i = 0; i < 4; i++)
                #pragma unroll
                for (int c = 0; c < 4; c++)
                    s[i][c] += qv[i] * kv[c];
        }
        #pragma unroll
        for (int i = 0; i < 4; i++)
            #pragma unroll
            for (int c = 0; c < 4; c++) {
                s[i][c] *= 0.125f;
                if (j == qt && (k0 + tx * 4 + c) > (q0 + ty * 4 + i)) s[i][c] = -1e30f;
            }
        __syncthreads();
        #pragma unroll
        for (int i = 0; i < 4; i++)
            #pragma unroll
            for (int c = 0; c < 4; c++)
                Ks[(ty * 4 + i) * 64 + tx * 4 + c] = s[i][c];
        __syncthreads();

        if (tid < 64) {
            float m_old = rowm[tid], m = m_old;
            #pragma unroll 8
            for (int t = 0; t < 64; t++) {
                int kk = (t + tid) & 63;
                m = fmaxf(m, Ks[tid * 64 + kk]);
            }
            float f = __expf(m_old - m);
            float l = rowl[tid] * f;
            #pragma unroll 8
            for (int t = 0; t < 64; t++) {
                int kk = (t + tid) & 63;
                float p = __expf(Ks[tid * 64 + kk] - m);
                Ks[tid * 64 + kk] = p;
                l += p;
            }
            rowm[tid] = m; rowl[tid] = l; rowf[tid] = f;
        }
        __syncthreads();

        float fr[4];
        #pragma unroll
        for (int i = 0; i < 4; i++) fr[i] = rowf[ty * 4 + i];
        #pragma unroll
        for (int i = 0; i < 4; i++)
            #pragma unroll
            for (int c = 0; c < 4; c++) o[i][c] *= fr[i];
        #pragma unroll 8
        for (int kk = 0; kk < 64; kk++) {
            float p[4];
            #pragma unroll
            for (int i = 0; i < 4; i++) p[i] = Ks[(ty * 4 + i) * 64 + kk];
            float4 vv = *(const float4*)&Vs[kk * 64 + tx * 4];
            #pragma unroll
            for (int i = 0; i < 4; i++) {
                o[i][0] += p[i] * vv.x; o[i][1] += p[i] * vv.y;
                o[i][2] += p[i] * vv.z; o[i][3] += p[i] * vv.w;
            }
        }
    }

    #pragma unroll
    for (int i = 0; i < 4; i++) {
        float inv = 1.0f / rowl[ty * 4 + i];
        float v0 = o[i][0] * inv, v1 = o[i][1] * inv;
        float v2 = o[i][2] * inv, v3 = o[i][3] * inv;
        uint32_t h01, l01, h23, l23;
        split2(v0, v1, h01, l01);
        split2(v2, v3, h23, l23);
        long base = ((long)(b * SQ + q0 + ty * 4 + i)) * DQ + h * HDQ + tx * 4;
        *(uint2*)&ctxh[base] = make_uint2(h01, h23);
        *(uint2*)&ctxl[base] = make_uint2(l01, l23);
    }
}

// ---------------- host orchestration ----------------
extern "C" void kernel_launch(void* const* d_in, const int* in_sizes, int n_in,
                              void* d_out, int out_size) {
    const int*   x    = (const int*)  d_in[0];
    const float* tok  = (const float*)d_in[1];
    const float* pos  = (const float*)d_in[2];
    const float* ln1s = (const float*)d_in[3];
    const float* ln1b = (const float*)d_in[4];
    const float* wq   = (const float*)d_in[5];
    const float* wk   = (const float*)d_in[6];
    const float* wv   = (const float*)d_in[7];
    const float* wo   = (const float*)d_in[8];
    const float* bo   = (const float*)d_in[9];
    const float* ln2s = (const float*)d_in[10];
    const float* ln2b = (const float*)d_in[11];
    const float* w1   = (const float*)d_in[12];
    const float* b1   = (const float*)d_in[13];
    const float* w2   = (const float*)d_in[14];
    const float* b2   = (const float*)d_in[15];
    const float* fs   = (const float*)d_in[16];
    const float* fb   = (const float*)d_in[17];
    const float* wout = (const float*)d_in[18];
    float* out = (float*)d_out;

    float *h, *q, *k, *v;
    uint16_t *hnh, *hnl, *ctxh, *ctxl, *ffh, *ffl, *wth, *wtl;
    cudaGetSymbolAddress((void**)&h,    g_h);
    cudaGetSymbolAddress((void**)&q,    g_q);
    cudaGetSymbolAddress((void**)&k,    g_k);
    cudaGetSymbolAddress((void**)&v,    g_v);
    cudaGetSymbolAddress((void**)&hnh,  g_hnh);
    cudaGetSymbolAddress((void**)&hnl,  g_hnl);
    cudaGetSymbolAddress((void**)&ctxh, g_ctxh);
    cudaGetSymbolAddress((void**)&ctxl, g_ctxl);
    cudaGetSymbolAddress((void**)&ffh,  g_ffh);
    cudaGetSymbolAddress((void**)&ffl,  g_ffl);
    cudaGetSymbolAddress((void**)&wth,  g_wth);
    cudaGetSymbolAddress((void**)&wtl,  g_wtl);

    const int FLASH_SMEM  = (64 * 64 * 3 + 64 * 3) * sizeof(float); // 49920
    const int SMEM128 = 2 * (2 * 128 + 256) * 80;  // 81920
    const int SMEM64  = 2 * (2 * 64 + 256) * 80;   // 61440
    cudaFuncSetAttribute(gpt_flash, cudaFuncAttributeMaxDynamicSharedMemorySize, FLASH_SMEM);
    cudaFuncSetAttribute((const void*)gpt_bmma<2, false, 64>,  cudaFuncAttributeMaxDynamicSharedMemorySize, SMEM64);
    cudaFuncSetAttribute((const void*)gpt_bmma<3, false, 128>, cudaFuncAttributeMaxDynamicSharedMemorySize, SMEM128);
    cudaFuncSetAttribute((const void*)gpt_bmma<0, true, 128>,  cudaFuncAttributeMaxDynamicSharedMemorySize, SMEM128);
    cudaFuncSetAttribute((const void*)gpt_bmma_qkv,            cudaFuncAttributeMaxDynamicSharedMemorySize, SMEM128);

    // ---- weight transpose+split, batched over layers ----
    dim3 wt(32, 8);
    gpt_wsplit<<<dim3(24, 24, 12), wt>>>(wq,  wth + WQ_OFF,  wtl + WQ_OFF,  DQ, DQ, DQ,
                                         (long)DQ*DQ,  (long)LSZ);
    gpt_wsplit<<<dim3(24, 24, 12), wt>>>(wk,  wth + WK_OFF,  wtl + WK_OFF,  DQ, DQ, DQ,
                                         (long)DQ*DQ,  (long)LSZ);
    gpt_wsplit<<<dim3(24, 24, 12), wt>>>(wv,  wth + WV_OFF,  wtl + WV_OFF,  DQ, DQ, DQ,
                                         (long)DQ*DQ,  (long)LSZ);
    gpt_wsplit<<<dim3(24, 24, 12), wt>>>(wo,  wth + WO_OFF,  wtl + WO_OFF,  DQ, DQ, DQ,
                                         (long)DQ*DQ,  (long)LSZ);
    gpt_wsplit<<<dim3(96, 24, 12), wt>>>(w1,  wth + W1T_OFF, wtl + W1T_OFF, DQ, FFQ, FFQ,
                                         (long)DQ*FFQ, (long)LSZ);
    gpt_wsplit<<<dim3(24, 96, 12), wt>>>(w2,  wth + W2T_OFF, wtl + W2T_OFF, FFQ, DQ, DQ,
                                         (long)FFQ*DQ, (long)LSZ);
    gpt_wsplit<<<dim3(VQP / 32, 24, 1), wt>>>(wout, wth + WOUT_OFF, wtl + WOUT_OFF,
                                         DQ, VQ, VQP, 0, 0);

    gpt_embed<<<(NT * DQ + 255) / 256, 256>>>(x, tok, pos, h);

    dim3 gP (DQ / 128,  NT / 64);         // (6,32)  BM=64: proj, ffn2
    dim3 gQ (DQ / 128,  NT / 128, 3);     // (6,16,3)
    dim3 gF1(FFQ / 128, NT / 128);        // (24,16)
    dim3 gV (VQP / 128, 4);               // (393,4) miter=4
    dim3 gFl(SQ / 64,   BQ * HQ);         // (8,48)

    for (int l = 0; l < LQ; l++) {
        long lo = (long)l * LSZ;

        gpt_ln<<<NT, 256>>>(h, ln1s + l * DQ, ln1b + l * DQ, hnh, hnl);

        gpt_bmma_qkv<<<gQ, 256, SMEM128>>>(hnh, hnl, wth + lo + WQ_OFF, wtl + lo + WQ_OFF,
                                           q, k, v);

        gpt_flash<<<gFl, 256, FLASH_SMEM>>>(q, k, v, ctxh, ctxl);

        gpt_bmma<2, false, 64><<<gP, 256, SMEM64>>>(ctxh, ctxl,
            wth + lo + WO_OFF, wtl + lo + WO_OFF, bo + l * DQ, h, h, nullptr, nullptr,
            DQ, DQ, DQ, 1);

        gpt_ln<<<NT, 256>>>(h, ln2s + l * DQ, ln2b + l * DQ, hnh, hnl);

        gpt_bmma<3, false, 128><<<gF1, 256, SMEM128>>>(hnh, hnl,
            wth + lo + W1T_OFF, wtl + lo + W1T_OFF, b1 + l * FFQ, nullptr,
            nullptr, ffh, ffl, FFQ, DQ, FFQ, 1);

        gpt_bmma<2, false, 64><<<gP, 256, SMEM64>>>(ffh, ffl,
            wth + lo + W2T_OFF, wtl + lo + W2T_OFF, b2 + l * DQ, h, h, nullptr, nullptr,
            DQ, FFQ, DQ, 1);
    }

    gpt_ln<<<NT, 256>>>(h, fs, fb, hnh, hnl);

    gpt_bmma<0, true, 128><<<gV, 256, SMEM128>>>(hnh, hnl,
        wth + WOUT_OFF, wtl + WOUT_OFF, nullptr, nullptr, out, nullptr, nullptr,
        VQ, DQ, VQ, 4);
}